// round 15
// baseline (speedup 1.0000x reference)
#include <cuda_runtime.h>
#include <cuda_fp16.h>
#include <math.h>
#include <stdint.h>

// Problem constants
#define T_  32
#define N_  64
#define H_  256

#define STRH 264    // h16 smem row stride (halfs)
#define STRW 104    // per-warp XI slice row stride (halfs): 96 + 8 pad

// ---------------------------------------------------------------------------
// Device scratch
// ---------------------------------------------------------------------------
__device__ __half g_XI16[2ull * 4096 * 768];        // [dir][m*64+n][3H] fp16
__device__ float  g_XF1[2048ull * 256];
__device__ float  g_XF2[2048ull * 256];
__device__ float  g_GI [2048ull * 768];             // cell gi fp32
__device__ __half g_K16[2048ull * 2 * 64 * 256];    // GRU outputs fp16
__device__ uint4  g_Bh4[4ull * 96 * 8 * 32];        // fp16 B-fragments: whf, whb, wif, wib
__device__ __half g_Wc16[768 * 256];                // cell_wh fp16 (row-major)
__device__ float  g_H2 [2048ull * 256];             // decoder h per (t,n) fp32
__device__ float  g_Q  [2048ull * 256];             // decoder q per (t,n) fp32

// ---------------------------------------------------------------------------
// helpers
// ---------------------------------------------------------------------------
__device__ __forceinline__ uint32_t packh2(float a, float b) {
    __half2 h = __floats2half2_rn(a, b);
    return *(uint32_t*)&h;
}

__device__ __forceinline__ void mma_f16(float* c, uint32_t a0, uint32_t a1, uint32_t a2,
                                        uint32_t a3, uint32_t b0, uint32_t b1) {
    asm volatile(
        "mma.sync.aligned.m16n8k16.row.col.f32.f16.f16.f32 "
        "{%0,%1,%2,%3}, {%4,%5,%6,%7}, {%8,%9}, {%0,%1,%2,%3};"
        : "+f"(c[0]), "+f"(c[1]), "+f"(c[2]), "+f"(c[3])
        : "r"(a0), "r"(a1), "r"(a2), "r"(a3), "r"(b0), "r"(b1));
}

__device__ __forceinline__ uint32_t smem_u32(const void* p) {
    return (uint32_t)__cvta_generic_to_shared(p);
}

// ---------------------------------------------------------------------------
// Permute four [768,256] weights into fp16 B-fragment order AND convert
// cell_wh to fp16 (merged).
// ---------------------------------------------------------------------------
__global__ __launch_bounds__(256)
void permute_w16(const float* __restrict__ whf, const float* __restrict__ whb,
                 const float* __restrict__ wif, const float* __restrict__ wib,
                 const float* __restrict__ cell_wh) {
    int idx = blockIdx.x * 256 + threadIdx.x;
    if (idx < 4 * 96 * 8 * 32) {
        int widx = idx / 24576;
        int r    = idx % 24576;
        int lane = r & 31;
        int kc2  = (r >> 5) & 7;
        int nt   = r >> 8;                       // 0..95
        int gr = lane >> 2, tig = lane & 3;
        const float* W = (widx == 0) ? whf : (widx == 1) ? whb : (widx == 2) ? wif : wib;
        const float* wr = W + (size_t)(nt * 8 + gr) * 256 + kc2 * 32 + 2 * tig;
        uint4 o;
        o.x = packh2(wr[0],  wr[1]);
        o.y = packh2(wr[8],  wr[9]);
        o.z = packh2(wr[16], wr[17]);
        o.w = packh2(wr[24], wr[25]);
        g_Bh4[idx] = o;
    } else {
        int i = idx - 4 * 96 * 8 * 32;
        if (i < 768 * 256) g_Wc16[i] = __float2half(cell_wh[i]);
    }
}

// ---------------------------------------------------------------------------
// XI projection via fp16 MMA (validated): XI = embed[lines] @ Wi^T + bi.
// ---------------------------------------------------------------------------
__global__ __launch_bounds__(512, 1)
void xi_mma(const int* __restrict__ lines, const float* __restrict__ embed,
            const float* __restrict__ bi_f, const float* __restrict__ bi_b)
{
    __shared__ __half a16[32 * STRH];
    __shared__ float  sbi[768];

    const int tid  = threadIdx.x;
    const int lane = tid & 31;
    const int w    = tid >> 5;
    const int w8   = w & 7;
    const int mh   = w >> 3;
    const int gr   = lane >> 2;
    const int tig  = lane & 3;

    const int d  = blockIdx.x >> 7;
    const int r0 = (blockIdx.x & 127) * 32;

    const float* bi = d ? bi_b : bi_f;
    for (int i = tid; i < 768; i += 512) sbi[i] = bi[i];

#pragma unroll
    for (int rw2 = 0; rw2 < 2; rw2++) {
        int row  = w * 2 + rw2;
        int grow = r0 + row;
        int m = grow >> 6, n = grow & 63;
        const float* src = embed + (size_t)lines[n * 64 + m] * 256 + lane * 8;
        float4 v0 = *(const float4*)(src);
        float4 v1 = *(const float4*)(src + 4);
        __half2* dst = (__half2*)&a16[row * STRH + lane * 8];
        dst[0] = __floats2half2_rn(v0.x, v0.y);
        dst[1] = __floats2half2_rn(v0.z, v0.w);
        dst[2] = __floats2half2_rn(v1.x, v1.y);
        dst[3] = __floats2half2_rn(v1.z, v1.w);
    }
    __syncthreads();

    const uint32_t abase = smem_u32(a16) + (uint32_t)((mh * 16 + (lane & 15)) * STRH * 2
                                                      + (lane >> 4) * 16);
    const uint4* bb = g_Bh4 + (size_t)(2 + d) * (96 * 8 * 32);

    float acc[3][4][4];
#pragma unroll
    for (int g = 0; g < 3; g++)
#pragma unroll
        for (int nt = 0; nt < 4; nt++)
#pragma unroll
            for (int i = 0; i < 4; i++) acc[g][nt][i] = 0.f;

#pragma unroll
    for (int kc2 = 0; kc2 < 8; kc2++) {
        uint32_t a0[4], a1[4];
        uint32_t addr = abase + (uint32_t)(kc2 * 64);
        asm volatile("ldmatrix.sync.aligned.m8n8.x4.shared.b16 {%0,%1,%2,%3}, [%4];"
                     : "=r"(a0[0]), "=r"(a0[1]), "=r"(a0[2]), "=r"(a0[3]) : "r"(addr));
        asm volatile("ldmatrix.sync.aligned.m8n8.x4.shared.b16 {%0,%1,%2,%3}, [%4];"
                     : "=r"(a1[0]), "=r"(a1[1]), "=r"(a1[2]), "=r"(a1[3]) : "r"(addr + 32));
#pragma unroll
        for (int g = 0; g < 3; g++) {
            uint4 bv[4];
#pragma unroll
            for (int nt = 0; nt < 4; nt++)
                bv[nt] = __ldg(bb + ((size_t)((g * 32 + w8 * 4 + nt) * 8 + kc2)) * 32 + lane);
#pragma unroll
            for (int nt = 0; nt < 4; nt++) {
                mma_f16(acc[g][nt], a0[0], a0[1], a0[2], a0[3], bv[nt].x, bv[nt].y);
                mma_f16(acc[g][nt], a1[0], a1[1], a1[2], a1[3], bv[nt].z, bv[nt].w);
            }
        }
    }

    __half* xout = g_XI16 + (size_t)d * (4096ull * 768);
#pragma unroll
    for (int g = 0; g < 3; g++)
#pragma unroll
        for (int nt = 0; nt < 4; nt++) {
            const int colb = w8 * 32 + nt * 8 + 2 * tig;
#pragma unroll
            for (int rw = 0; rw < 2; rw++) {
                const int row = mh * 16 + rw * 8 + gr;
                float v0 = acc[g][nt][rw * 2 + 0] + sbi[g * 256 + colb];
                float v1 = acc[g][nt][rw * 2 + 1] + sbi[g * 256 + colb + 1];
                *(__half2*)(xout + (size_t)(r0 + row) * 768 + g * 256 + colb)
                    = __floats2half2_rn(v0, v1);
            }
        }
}

// ---------------------------------------------------------------------------
// Generic tiled fp32 GEMM (setup)
// ---------------------------------------------------------------------------
__global__ __launch_bounds__(256)
void gemm_k(int mode, const float* __restrict__ A, const float* __restrict__ B,
            const float* __restrict__ bias, float* __restrict__ C,
            int cols, int K, int relu,
            const float* __restrict__ cond, const float* __restrict__ aemb,
            const int* __restrict__ a_idx)
{
    __shared__ float As[32][36];
    __shared__ float Bs[32][132];

    const int row0 = blockIdx.x * 32;
    const int col0 = blockIdx.y * 128;
    const int tid  = threadIdx.x;
    const int tx   = tid & 31;
    const int ty   = tid >> 5;

    const int lr  = tid >> 3;
    const int lk4 = (tid & 7) * 4;
    const int grow = row0 + lr;

    const float* Arow = nullptr;
    int ap = 0;
    if (mode == 1) {
        int t = grow >> 6;
        ap = (t == 0) ? 0 : a_idx[grow - 64];
    } else {
        Arow = A + (size_t)grow * K;
    }

    const int cc  = tid >> 1;
    const int kk0 = (tid & 1) * 16;
    const float* Brow0 = B + (size_t)(col0 + cc) * K;

    float acc[4][4];
#pragma unroll
    for (int i = 0; i < 4; i++)
#pragma unroll
        for (int j = 0; j < 4; j++) acc[i][j] = 0.f;

    for (int k0 = 0; k0 < K; k0 += 32) {
        float4 av;
        if (mode == 1) {
            float t4[4];
#pragma unroll
            for (int i = 0; i < 4; i++) {
                int k = k0 + lk4 + i;
                t4[i] = (k < 64) ? cond[(size_t)grow * 64 + k]
                                 : aemb[(size_t)ap * 256 + (k - 64)];
            }
            av = make_float4(t4[0], t4[1], t4[2], t4[3]);
        } else {
            av = *(const float4*)(Arow + k0 + lk4);
        }
        As[lk4 + 0][lr] = av.x; As[lk4 + 1][lr] = av.y;
        As[lk4 + 2][lr] = av.z; As[lk4 + 3][lr] = av.w;

        const float* bp = Brow0 + k0 + kk0;
#pragma unroll
        for (int i = 0; i < 16; i += 4) {
            float4 bv = *(const float4*)(bp + i);
            Bs[kk0 + i + 0][cc] = bv.x; Bs[kk0 + i + 1][cc] = bv.y;
            Bs[kk0 + i + 2][cc] = bv.z; Bs[kk0 + i + 3][cc] = bv.w;
        }
        __syncthreads();

#pragma unroll
        for (int kk = 0; kk < 32; kk++) {
            float4 a = *(const float4*)&As[kk][ty * 4];
            float4 b = *(const float4*)&Bs[kk][tx * 4];
            acc[0][0] += a.x * b.x; acc[0][1] += a.x * b.y; acc[0][2] += a.x * b.z; acc[0][3] += a.x * b.w;
            acc[1][0] += a.y * b.x; acc[1][1] += a.y * b.y; acc[1][2] += a.y * b.z; acc[1][3] += a.y * b.w;
            acc[2][0] += a.z * b.x; acc[2][1] += a.z * b.y; acc[2][2] += a.z * b.z; acc[2][3] += a.z * b.w;
            acc[3][0] += a.w * b.x; acc[3][1] += a.w * b.y; acc[3][2] += a.w * b.z; acc[3][3] += a.w * b.w;
        }
        __syncthreads();
    }

#pragma unroll
    for (int i = 0; i < 4; i++) {
        int row = row0 + ty * 4 + i;
        float4 v = make_float4(acc[i][0], acc[i][1], acc[i][2], acc[i][3]);
        if (bias) {
            int c = col0 + tx * 4;
            v.x += bias[c]; v.y += bias[c + 1]; v.z += bias[c + 2]; v.w += bias[c + 3];
        }
        if (relu) {
            v.x = fmaxf(v.x, 0.f); v.y = fmaxf(v.y, 0.f);
            v.z = fmaxf(v.z, 0.f); v.w = fmaxf(v.w, 0.f);
        }
        *(float4*)(C + (size_t)row * cols + col0 + tx * 4) = v;
    }
}

// ---------------------------------------------------------------------------
// Persistent bidirectional GRU recurrence — EXACT R11 version (993us proven).
// ---------------------------------------------------------------------------
__global__ __launch_bounds__(512, 1)
void recur_kernel(const int* __restrict__ p_idx,
                  const float* __restrict__ bh_f, const float* __restrict__ bh_b)
{
    extern __shared__ char smraw[];
    __half* h16  = (__half*)smraw;                               // 2 x 32*STRH halfs
    float*  sbh  = (float*)(smraw + 2 * 32 * STRH * 2);          // 768 floats
    __half* sXI  = (__half*)(sbh + 768);                         // 16 warps x 16 x STRW halfs
    int*    rrs  = (int*)(sXI + 16 * 16 * STRW);                 // 32 ints

    const int tid  = threadIdx.x;
    const int lane = tid & 31;
    const int w    = tid >> 5;        // 0..15
    const int w8   = w & 7;
    const int mh   = w >> 3;
    const int gr   = lane >> 2;
    const int tig  = lane & 3;

    const int d  = blockIdx.x >> 6;            // direction
    const int c0 = (blockIdx.x & 63) * 32;     // chain base within direction

    const float* bh = d ? bh_b : bh_f;
    for (int i = tid; i < 768; i += 512) sbh[i] = bh[i];
    for (int i = tid; i < 32 * STRH; i += 512) ((uint32_t*)h16)[i] = 0u;  // both buffers
    if (tid < 32) rrs[tid] = p_idx[c0 + tid];

    const uint32_t aoff = (uint32_t)((mh * 16 + (lane & 15)) * STRH * 2 + (lane >> 4) * 16);
    const uint32_t abase0 = smem_u32(h16) + aoff;
    const uint32_t abase1 = smem_u32(h16 + 32 * STRH) + aoff;

    __half* sxw = sXI + w * 16 * STRW;
    const uint32_t sxw_b = smem_u32(sxw);

    const uint4* bb = g_Bh4 + (size_t)d * (96 * 8 * 32);

    float hold[2][4][2];
#pragma unroll
    for (int a = 0; a < 2; a++)
#pragma unroll
        for (int b = 0; b < 4; b++) { hold[a][b][0] = 0.f; hold[a][b][1] = 0.f; }

    __syncthreads();

    for (int j = 0; j < 64; j++) {
#pragma unroll
        for (int it = 0; it < 6; it++) {
            int id   = it * 32 + lane;
            int lrow = id & 15;
            int rem  = id >> 4;
            int gate = rem >> 2;
            int q    = rem & 3;
            int grow = mh * 16 + lrow;
            int rr   = rrs[grow];
            int m    = (d == 0) ? ((j - rr + 64) & 63) : ((63 - j - rr + 128) & 63);
            int n    = (c0 + grow) & 63;
            const __half* src = g_XI16 + ((size_t)d * 4096 + m * 64 + n) * 768
                                + gate * 256 + w8 * 32 + q * 8;
            uint32_t dst = sxw_b + (uint32_t)(lrow * (STRW * 2) + gate * 64 + q * 16);
            asm volatile("cp.async.cg.shared.global [%0], [%1], 16;"
                         :: "r"(dst), "l"(src));
        }
        asm volatile("cp.async.commit_group;");

        const uint32_t abase = (j & 1) ? abase1 : abase0;
        float acc[3][4][4];
#pragma unroll
        for (int g = 0; g < 3; g++)
#pragma unroll
            for (int nt = 0; nt < 4; nt++)
#pragma unroll
                for (int i = 0; i < 4; i++) acc[g][nt][i] = 0.f;

#pragma unroll
        for (int kc2 = 0; kc2 < 8; kc2++) {
            uint32_t a0[4], a1[4];
            {
                uint32_t addr = abase + (uint32_t)(kc2 * 64);
                asm volatile("ldmatrix.sync.aligned.m8n8.x4.shared.b16 {%0,%1,%2,%3}, [%4];"
                             : "=r"(a0[0]), "=r"(a0[1]), "=r"(a0[2]), "=r"(a0[3]) : "r"(addr));
                asm volatile("ldmatrix.sync.aligned.m8n8.x4.shared.b16 {%0,%1,%2,%3}, [%4];"
                             : "=r"(a1[0]), "=r"(a1[1]), "=r"(a1[2]), "=r"(a1[3]) : "r"(addr + 32));
            }
#pragma unroll
            for (int g = 0; g < 3; g++) {
                uint4 bv[4];
#pragma unroll
                for (int nt = 0; nt < 4; nt++)
                    bv[nt] = __ldg(bb + ((size_t)((g * 32 + w8 * 4 + nt) * 8 + kc2)) * 32 + lane);
#pragma unroll
                for (int nt = 0; nt < 4; nt++) {
                    mma_f16(acc[g][nt], a0[0], a0[1], a0[2], a0[3], bv[nt].x, bv[nt].y);
                    mma_f16(acc[g][nt], a1[0], a1[1], a1[2], a1[3], bv[nt].z, bv[nt].w);
                }
            }
        }

        asm volatile("cp.async.wait_group 0;" ::: "memory");
        __syncwarp();

        __half* hnext = h16 + ((j & 1) ^ 1) * (32 * STRH);
#pragma unroll
        for (int nt = 0; nt < 4; nt++) {
            const int lcol = nt * 8 + 2 * tig;
            const int colb = w8 * 32 + lcol;
#pragma unroll
            for (int rw = 0; rw < 2; rw++) {
                const int lrow = rw * 8 + gr;
                const int row  = mh * 16 + lrow;
                const __half* xr = sxw + lrow * STRW + lcol;
                float2 xir = __half22float2(*(const __half2*)(xr));
                float2 xiz = __half22float2(*(const __half2*)(xr + 32));
                float2 xin = __half22float2(*(const __half2*)(xr + 64));

                float ghr0 = acc[0][nt][rw * 2 + 0] + sbh[colb];
                float ghr1 = acc[0][nt][rw * 2 + 1] + sbh[colb + 1];
                float ghz0 = acc[1][nt][rw * 2 + 0] + sbh[256 + colb];
                float ghz1 = acc[1][nt][rw * 2 + 1] + sbh[256 + colb + 1];
                float ghn0 = acc[2][nt][rw * 2 + 0] + sbh[512 + colb];
                float ghn1 = acc[2][nt][rw * 2 + 1] + sbh[512 + colb + 1];

                float r0 = __fdividef(1.f, 1.f + __expf(-(xir.x + ghr0)));
                float r1 = __fdividef(1.f, 1.f + __expf(-(xir.y + ghr1)));
                float z0 = __fdividef(1.f, 1.f + __expf(-(xiz.x + ghz0)));
                float z1 = __fdividef(1.f, 1.f + __expf(-(xiz.y + ghz1)));
                float n0, n1;
                asm("tanh.approx.f32 %0, %1;" : "=f"(n0) : "f"(xin.x + r0 * ghn0));
                asm("tanh.approx.f32 %0, %1;" : "=f"(n1) : "f"(xin.y + r1 * ghn1));

                float h0 = (1.f - z0) * n0 + z0 * hold[rw][nt][0];
                float h1 = (1.f - z1) * n1 + z1 * hold[rw][nt][1];
                hold[rw][nt][0] = h0;
                hold[rw][nt][1] = h1;

                __half2 hh = __floats2half2_rn(h0, h1);
                *(__half2*)&hnext[row * STRH + colb] = hh;
                *(__half2*)(g_K16 + ((((size_t)(c0 + row)) * 2 + d) * 64 + j) * 256 + colb) = hh;
            }
        }
        __syncthreads();
    }
}

// ---------------------------------------------------------------------------
// matvec: fp32 weights, float4 loads (8 warps)
// ---------------------------------------------------------------------------
__device__ __forceinline__ void matvec8(float* __restrict__ y,
                                        const float* __restrict__ W,
                                        const float* __restrict__ b,
                                        const float* __restrict__ x,
                                        int Nout, int K)
{
    int tid  = threadIdx.x;
    int lane = tid & 31, warp = tid >> 5;
    int s = lane & 7, og = lane >> 3;
    for (int ob = warp * 4; ob < Nout; ob += 32) {
        int o = ob + og;
        bool valid = (o < Nout);
        const float* w = W + (size_t)(valid ? o : ob) * K;
        float acc = 0.f;
        for (int k = s * 4; k < K; k += 32) {
            float4 wv = *(const float4*)(w + k);
            float4 xv = *(const float4*)(x + k);
            acc += wv.x * xv.x + wv.y * xv.y + wv.z * xv.z + wv.w * xv.w;
        }
        acc += __shfl_down_sync(0xffffffffu, acc, 4);
        acc += __shfl_down_sync(0xffffffffu, acc, 2);
        acc += __shfl_down_sync(0xffffffffu, acc, 1);
        if (s == 0 && valid) y[o] = b ? (acc + b[o]) : acc;
    }
}

// ---------------------------------------------------------------------------
// matvec: fp16 weights, LDG.128, K=256, NW warps
// ---------------------------------------------------------------------------
template <int NW>
__device__ __forceinline__ void matvec8h16(float* __restrict__ y,
                                           const __half* __restrict__ W,
                                           const float* __restrict__ b,
                                           const float* __restrict__ x,
                                           int Nout)
{
    int tid  = threadIdx.x;
    int lane = tid & 31, warp = tid >> 5;
    int s = lane & 7, og = lane >> 3;
    for (int ob = warp * 4; ob < Nout; ob += NW * 4) {
        int o = ob + og;
        bool valid = (o < Nout);
        const uint4* w4 = (const uint4*)(W + (size_t)(valid ? o : ob) * 256);
        float acc = 0.f;
#pragma unroll
        for (int it = 0; it < 4; it++) {
            int k = s * 8 + it * 64;
            uint4 wv = __ldg(w4 + (k >> 3));
            const __half2* hp = (const __half2*)&wv;
            float4 xa = *(const float4*)(x + k);
            float4 xb = *(const float4*)(x + k + 4);
            float2 w0 = __half22float2(hp[0]);
            float2 w1 = __half22float2(hp[1]);
            float2 w2 = __half22float2(hp[2]);
            float2 w3 = __half22float2(hp[3]);
            acc += w0.x * xa.x + w0.y * xa.y + w1.x * xa.z + w1.y * xa.w
                 + w2.x * xb.x + w2.y * xb.y + w3.x * xb.z + w3.y * xb.w;
        }
        acc += __shfl_down_sync(0xffffffffu, acc, 4);
        acc += __shfl_down_sync(0xffffffffu, acc, 2);
        acc += __shfl_down_sync(0xffffffffu, acc, 1);
        if (s == 0 && valid) y[o] = b ? (acc + b[o]) : acc;
    }
}

// ---------------------------------------------------------------------------
// D1: decoder h-recurrence, 4 chains per block (weight reuse x4).
// 16 blocks x 512 threads. Each weight uint4 load feeds 4 dot products.
// Per-chain arithmetic order identical to the single-chain version.
// ---------------------------------------------------------------------------
__global__ __launch_bounds__(512)
void decoder_h4(const float* __restrict__ cell_bh)
{
    const int n0 = blockIdx.x * 4;
    const int tid = threadIdx.x;

    __shared__ float sh_h [4][256];
    __shared__ float sh_gh[4][768];

    for (int i = tid; i < 4 * 256; i += 512) ((float*)sh_h)[i] = 0.f;
    __syncthreads();

    const int lane = tid & 31, warp = tid >> 5;
    const int s = lane & 7, og = lane >> 3;

    for (int t = 0; t < T_; t++) {
        // gates for 4 chains: one weight load, 4 dots
        for (int ob = warp * 4; ob < 768; ob += 64) {
            int o = ob + og;
            const uint4* w4 = (const uint4*)(g_Wc16 + (size_t)o * 256);
            float acc[4] = {0.f, 0.f, 0.f, 0.f};
#pragma unroll
            for (int it = 0; it < 4; it++) {
                int k = s * 8 + it * 64;
                uint4 wv = __ldg(w4 + (k >> 3));
                const __half2* hp = (const __half2*)&wv;
                float2 w0 = __half22float2(hp[0]);
                float2 w1 = __half22float2(hp[1]);
                float2 w2 = __half22float2(hp[2]);
                float2 w3 = __half22float2(hp[3]);
#pragma unroll
                for (int c = 0; c < 4; c++) {
                    float4 xa = *(const float4*)&sh_h[c][k];
                    float4 xb = *(const float4*)&sh_h[c][k + 4];
                    acc[c] += w0.x * xa.x + w0.y * xa.y + w1.x * xa.z + w1.y * xa.w
                            + w2.x * xb.x + w2.y * xb.y + w3.x * xb.z + w3.y * xb.w;
                }
            }
#pragma unroll
            for (int c = 0; c < 4; c++) {
                acc[c] += __shfl_down_sync(0xffffffffu, acc[c], 4);
                acc[c] += __shfl_down_sync(0xffffffffu, acc[c], 2);
                acc[c] += __shfl_down_sync(0xffffffffu, acc[c], 1);
            }
            if (s == 0) {
                float bb = cell_bh[o];
#pragma unroll
                for (int c = 0; c < 4; c++) sh_gh[c][o] = acc[c] + bb;
            }
        }
        __syncthreads();

        // GRU update: 4 chains x 256 dims = 1024 items over 512 threads
#pragma unroll
        for (int rep = 0; rep < 2; rep++) {
            int item = rep * 512 + tid;
            int c  = item >> 8;
            int hh = item & 255;
            int n  = n0 + c;
            const float* gi = g_GI + (size_t)(t * 64 + n) * 768;
            float h_old = sh_h[c][hh];
            float rg = 1.f / (1.f + __expf(-(gi[hh]       + sh_gh[c][hh])));
            float zg = 1.f / (1.f + __expf(-(gi[256 + hh] + sh_gh[c][256 + hh])));
            float tn;
            asm("tanh.approx.f32 %0, %1;" : "=f"(tn) : "f"(gi[512 + hh] + rg * sh_gh[c][512 + hh]));
            float hnew = (1.f - zg) * tn + zg * h_old;
            sh_h[c][hh] = hnew;
            g_H2[(size_t)(t * 64 + n) * 256 + hh] = hnew;
        }
        __syncthreads();
    }
}

// ---------------------------------------------------------------------------
// D2: fully parallel heads + attention, one block per (t,n). 2048 blocks.
// ---------------------------------------------------------------------------
__global__ __launch_bounds__(256)
void decoder_heads(const float* __restrict__ pointer_w, const float* __restrict__ pointer_b,
                   const float* __restrict__ actor_w, const float* __restrict__ actor_b,
                   const float* __restrict__ critic_w, const float* __restrict__ critic_b,
                   const int* __restrict__ a_idx, const int* __restrict__ p_idx,
                   float* __restrict__ out)
{
    const int tn = blockIdx.x;            // t*64 + n
    const int tid = threadIdx.x;

    __shared__ float sh_h[256];
    __shared__ float sh_q[256];
    __shared__ float sh_l[128];
    __shared__ float sh_zz[256];
    __shared__ float sh_pl[64];
    __shared__ float sh_al[16];
    __shared__ float sh_v[4];
    __shared__ float s_max, s_sum;

    sh_h[tid] = g_H2[(size_t)tn * 256 + tid];
    sh_q[tid] = g_Q [(size_t)tn * 256 + tid];
    __syncthreads();

    matvec8(sh_pl, pointer_w, pointer_b, sh_h, 64, 256);
    matvec8(sh_v,  critic_w,  critic_b,  sh_h, 1, 256);

    const __half* Kc = g_K16 + (size_t)tn * (2 * 64 * 256);   // [128][256] fp16
    matvec8h16<8>(sh_l, Kc, nullptr, sh_q, 128);
    __syncthreads();

    if (tid < 32) {
        float m = fmaxf(sh_pl[tid], sh_pl[tid + 32]);
#pragma unroll
        for (int o = 16; o > 0; o >>= 1) m = fmaxf(m, __shfl_xor_sync(0xffffffffu, m, o));
        if (tid == 0) s_max = m;
    }
    __syncthreads();
    if (tid < 64) sh_pl[tid] = __expf(sh_pl[tid] - s_max);
    __syncthreads();
    if (tid < 32) {
        float s = sh_pl[tid] + sh_pl[tid + 32];
#pragma unroll
        for (int o = 16; o > 0; o >>= 1) s += __shfl_xor_sync(0xffffffffu, s, o);
        if (tid == 0) s_sum = s;
    }

    {
        float acc = 0.f;
#pragma unroll 8
        for (int k2 = 0; k2 < 128; k2++)
            acc += sh_l[k2] * __half2float(Kc[(size_t)k2 * 256 + tid]);
        sh_zz[tid] = acc;
    }
    __syncthreads();

    matvec8(sh_al, actor_w, actor_b, sh_zz, 16, 256);
    __syncthreads();
    if (tid < 32) {
        float v = (tid < 16) ? sh_al[tid] : -1e30f;
        float m = v;
#pragma unroll
        for (int o = 16; o > 0; o >>= 1) m = fmaxf(m, __shfl_xor_sync(0xffffffffu, m, o));
        float e = (tid < 16) ? __expf(v - m) : 0.f;
        float s = e;
#pragma unroll
        for (int o = 16; o > 0; o >>= 1) s += __shfl_xor_sync(0xffffffffu, s, o);
        if (tid < 16) sh_al[tid] = e / s;
    }
    __syncthreads();

    float* orow = out + (size_t)tn * 339;
    if (tid == 0) {
        orow[0] = (float)a_idx[tn];
        orow[1] = (float)p_idx[tn];
        orow[2] = sh_v[0];
    }
    orow[3 + tid] = sh_h[tid];
    if (tid < 16) orow[259 + tid] = sh_al[tid];
    if (tid < 64) orow[275 + tid] = sh_pl[tid] / s_sum;
}

// ---------------------------------------------------------------------------
// Launch — single stream (R11 proven structure; overlap retired for good).
// ONE change vs R11: decoder_h4 replaces decoder_h.
// ---------------------------------------------------------------------------
extern "C" void kernel_launch(void* const* d_in, const int* in_sizes, int n_in,
                              void* d_out, int out_size)
{
    const float* condition = (const float*)d_in[0];
    const int*   lines     = (const int*)  d_in[1];
    const int*   a_idx     = (const int*)  d_in[2];
    const int*   p_idx     = (const int*)  d_in[3];
    const float* embed     = (const float*)d_in[4];
    const float* aemb      = (const float*)d_in[5];
    const float* gru_wi_f  = (const float*)d_in[6];
    const float* gru_wh_f  = (const float*)d_in[7];
    const float* gru_bi_f  = (const float*)d_in[8];
    const float* gru_bh_f  = (const float*)d_in[9];
    const float* gru_wi_b  = (const float*)d_in[10];
    const float* gru_wh_b  = (const float*)d_in[11];
    const float* gru_bi_b  = (const float*)d_in[12];
    const float* gru_bh_b  = (const float*)d_in[13];
    const float* f_w1      = (const float*)d_in[14];
    const float* f_b1      = (const float*)d_in[15];
    const float* f_w2      = (const float*)d_in[16];
    const float* f_b2      = (const float*)d_in[17];
    const float* cell_wi   = (const float*)d_in[18];
    const float* cell_wh   = (const float*)d_in[19];
    const float* cell_bi   = (const float*)d_in[20];
    const float* cell_bh   = (const float*)d_in[21];
    const float* critic_w  = (const float*)d_in[22];
    const float* critic_b  = (const float*)d_in[23];
    const float* pointer_w = (const float*)d_in[24];
    const float* pointer_b = (const float*)d_in[25];
    const float* actor_w   = (const float*)d_in[26];
    const float* actor_b   = (const float*)d_in[27];
    const float* query_w   = (const float*)d_in[28];
    const float* query_b   = (const float*)d_in[29];
    float* out = (float*)d_out;

    void *pXF1_, *pXF2_, *pGI_, *pH2_, *pQ_;
    cudaGetSymbolAddress(&pXF1_, g_XF1);
    cudaGetSymbolAddress(&pXF2_, g_XF2);
    cudaGetSymbolAddress(&pGI_,  g_GI);
    cudaGetSymbolAddress(&pH2_,  g_H2);
    cudaGetSymbolAddress(&pQ_,   g_Q);
    float* pXF1 = (float*)pXF1_;
    float* pXF2 = (float*)pXF2_;
    float* pGI  = (float*)pGI_;
    float* pH2  = (float*)pH2_;
    float* pQ   = (float*)pQ_;

    const int SMEM_REC = 2 * 32 * STRH * 2 + 768 * 4 + 16 * 16 * STRW * 2 + 32 * 4;
    cudaFuncSetAttribute(recur_kernel, cudaFuncAttributeMaxDynamicSharedMemorySize, SMEM_REC);

    // (1) permute + cvt, (2) xi_mma, (3-5) MLP gemms, (6) recur
    permute_w16<<<1152, 256>>>(gru_wh_f, gru_wh_b, gru_wi_f, gru_wi_b, cell_wh);
    xi_mma<<<256, 512>>>(lines, embed, gru_bi_f, gru_bi_b);
    gemm_k<<<dim3(64, 2), 256>>>(1, nullptr, f_w1, f_b1, pXF1,
                                 256, 320, 1, condition, aemb, a_idx);
    gemm_k<<<dim3(64, 2), 256>>>(2, pXF1, f_w2, f_b2, pXF2,
                                 256, 256, 1, nullptr, nullptr, nullptr);
    gemm_k<<<dim3(64, 6), 256>>>(2, pXF2, cell_wi, cell_bi, pGI,
                                 768, 256, 0, nullptr, nullptr, nullptr);

    recur_kernel<<<128, 512, SMEM_REC>>>(p_idx, gru_bh_f, gru_bh_b);

    decoder_h4<<<16, 512>>>(cell_bh);
    gemm_k<<<dim3(64, 2), 256>>>(2, pH2, query_w, query_b, pQ,
                                 256, 256, 0, nullptr, nullptr, nullptr);
    decoder_heads<<<2048, 256>>>(pointer_w, pointer_b, actor_w, actor_b,
                                 critic_w, critic_b, a_idx, p_idx, out);
}

// round 16
// speedup vs baseline: 1.6332x; 1.6332x over previous
#include <cuda_runtime.h>
#include <cuda_fp16.h>
#include <math.h>
#include <stdint.h>

// Problem constants
#define T_  32
#define N_  64
#define H_  256

#define STRH 264    // h16 smem row stride (halfs)
#define STRW 104    // per-warp XI slice row stride (halfs): 96 + 8 pad

// ---------------------------------------------------------------------------
// Device scratch
// ---------------------------------------------------------------------------
__device__ __half g_XI16[2ull * 4096 * 768];        // [dir][m*64+n][3H] fp16
__device__ float  g_XF1[2048ull * 256];
__device__ float  g_XF2[2048ull * 256];
__device__ float  g_GI [2048ull * 768];             // cell gi fp32
__device__ __half g_K16[2048ull * 2 * 64 * 256];    // GRU outputs fp16
__device__ uint4  g_Bh4[4ull * 96 * 8 * 32];        // fp16 B-fragments: whf, whb, wif, wib
__device__ __half g_Wc16[768 * 256];                // cell_wh fp16 (row-major)
__device__ float  g_H2 [2048ull * 256];             // decoder h per (t,n) fp32
__device__ float  g_Q  [2048ull * 256];             // decoder q per (t,n) fp32

// ---------------------------------------------------------------------------
// helpers
// ---------------------------------------------------------------------------
__device__ __forceinline__ uint32_t packh2(float a, float b) {
    __half2 h = __floats2half2_rn(a, b);
    return *(uint32_t*)&h;
}

__device__ __forceinline__ void mma_f16(float* c, uint32_t a0, uint32_t a1, uint32_t a2,
                                        uint32_t a3, uint32_t b0, uint32_t b1) {
    asm volatile(
        "mma.sync.aligned.m16n8k16.row.col.f32.f16.f16.f32 "
        "{%0,%1,%2,%3}, {%4,%5,%6,%7}, {%8,%9}, {%0,%1,%2,%3};"
        : "+f"(c[0]), "+f"(c[1]), "+f"(c[2]), "+f"(c[3])
        : "r"(a0), "r"(a1), "r"(a2), "r"(a3), "r"(b0), "r"(b1));
}

__device__ __forceinline__ uint32_t smem_u32(const void* p) {
    return (uint32_t)__cvta_generic_to_shared(p);
}

// ---------------------------------------------------------------------------
// Permute four [768,256] weights into fp16 B-fragment order (R11 version).
// ---------------------------------------------------------------------------
__global__ __launch_bounds__(256)
void permute_w16(const float* __restrict__ whf, const float* __restrict__ whb,
                 const float* __restrict__ wif, const float* __restrict__ wib) {
    int idx = blockIdx.x * 256 + threadIdx.x;
    if (idx >= 4 * 96 * 8 * 32) return;
    int widx = idx / 24576;
    int r    = idx % 24576;
    int lane = r & 31;
    int kc2  = (r >> 5) & 7;
    int nt   = r >> 8;                       // 0..95
    int gr = lane >> 2, tig = lane & 3;
    const float* W = (widx == 0) ? whf : (widx == 1) ? whb : (widx == 2) ? wif : wib;
    const float* wr = W + (size_t)(nt * 8 + gr) * 256 + kc2 * 32 + 2 * tig;
    uint4 o;
    o.x = packh2(wr[0],  wr[1]);
    o.y = packh2(wr[8],  wr[9]);
    o.z = packh2(wr[16], wr[17]);
    o.w = packh2(wr[24], wr[25]);
    g_Bh4[idx] = o;
}

__global__ __launch_bounds__(256)
void cvt_cellwh(const float* __restrict__ cell_wh) {
    int i = blockIdx.x * 256 + threadIdx.x;
    if (i < 768 * 256) g_Wc16[i] = __float2half(cell_wh[i]);
}

// ---------------------------------------------------------------------------
// XI projection via fp16 MMA (validated): XI = embed[lines] @ Wi^T + bi.
// ---------------------------------------------------------------------------
__global__ __launch_bounds__(512, 1)
void xi_mma(const int* __restrict__ lines, const float* __restrict__ embed,
            const float* __restrict__ bi_f, const float* __restrict__ bi_b)
{
    __shared__ __half a16[32 * STRH];
    __shared__ float  sbi[768];

    const int tid  = threadIdx.x;
    const int lane = tid & 31;
    const int w    = tid >> 5;
    const int w8   = w & 7;
    const int mh   = w >> 3;
    const int gr   = lane >> 2;
    const int tig  = lane & 3;

    const int d  = blockIdx.x >> 7;
    const int r0 = (blockIdx.x & 127) * 32;

    const float* bi = d ? bi_b : bi_f;
    for (int i = tid; i < 768; i += 512) sbi[i] = bi[i];

#pragma unroll
    for (int rw2 = 0; rw2 < 2; rw2++) {
        int row  = w * 2 + rw2;
        int grow = r0 + row;
        int m = grow >> 6, n = grow & 63;
        const float* src = embed + (size_t)lines[n * 64 + m] * 256 + lane * 8;
        float4 v0 = *(const float4*)(src);
        float4 v1 = *(const float4*)(src + 4);
        __half2* dst = (__half2*)&a16[row * STRH + lane * 8];
        dst[0] = __floats2half2_rn(v0.x, v0.y);
        dst[1] = __floats2half2_rn(v0.z, v0.w);
        dst[2] = __floats2half2_rn(v1.x, v1.y);
        dst[3] = __floats2half2_rn(v1.z, v1.w);
    }
    __syncthreads();

    const uint32_t abase = smem_u32(a16) + (uint32_t)((mh * 16 + (lane & 15)) * STRH * 2
                                                      + (lane >> 4) * 16);
    const uint4* bb = g_Bh4 + (size_t)(2 + d) * (96 * 8 * 32);

    float acc[3][4][4];
#pragma unroll
    for (int g = 0; g < 3; g++)
#pragma unroll
        for (int nt = 0; nt < 4; nt++)
#pragma unroll
            for (int i = 0; i < 4; i++) acc[g][nt][i] = 0.f;

#pragma unroll
    for (int kc2 = 0; kc2 < 8; kc2++) {
        uint32_t a0[4], a1[4];
        uint32_t addr = abase + (uint32_t)(kc2 * 64);
        asm volatile("ldmatrix.sync.aligned.m8n8.x4.shared.b16 {%0,%1,%2,%3}, [%4];"
                     : "=r"(a0[0]), "=r"(a0[1]), "=r"(a0[2]), "=r"(a0[3]) : "r"(addr));
        asm volatile("ldmatrix.sync.aligned.m8n8.x4.shared.b16 {%0,%1,%2,%3}, [%4];"
                     : "=r"(a1[0]), "=r"(a1[1]), "=r"(a1[2]), "=r"(a1[3]) : "r"(addr + 32));
#pragma unroll
        for (int g = 0; g < 3; g++) {
            uint4 bv[4];
#pragma unroll
            for (int nt = 0; nt < 4; nt++)
                bv[nt] = __ldg(bb + ((size_t)((g * 32 + w8 * 4 + nt) * 8 + kc2)) * 32 + lane);
#pragma unroll
            for (int nt = 0; nt < 4; nt++) {
                mma_f16(acc[g][nt], a0[0], a0[1], a0[2], a0[3], bv[nt].x, bv[nt].y);
                mma_f16(acc[g][nt], a1[0], a1[1], a1[2], a1[3], bv[nt].z, bv[nt].w);
            }
        }
    }

    __half* xout = g_XI16 + (size_t)d * (4096ull * 768);
#pragma unroll
    for (int g = 0; g < 3; g++)
#pragma unroll
        for (int nt = 0; nt < 4; nt++) {
            const int colb = w8 * 32 + nt * 8 + 2 * tig;
#pragma unroll
            for (int rw = 0; rw < 2; rw++) {
                const int row = mh * 16 + rw * 8 + gr;
                float v0 = acc[g][nt][rw * 2 + 0] + sbi[g * 256 + colb];
                float v1 = acc[g][nt][rw * 2 + 1] + sbi[g * 256 + colb + 1];
                *(__half2*)(xout + (size_t)(r0 + row) * 768 + g * 256 + colb)
                    = __floats2half2_rn(v0, v1);
            }
        }
}

// ---------------------------------------------------------------------------
// Generic tiled fp32 GEMM (setup)
// ---------------------------------------------------------------------------
__global__ __launch_bounds__(256)
void gemm_k(int mode, const float* __restrict__ A, const float* __restrict__ B,
            const float* __restrict__ bias, float* __restrict__ C,
            int cols, int K, int relu,
            const float* __restrict__ cond, const float* __restrict__ aemb,
            const int* __restrict__ a_idx)
{
    __shared__ float As[32][36];
    __shared__ float Bs[32][132];

    const int row0 = blockIdx.x * 32;
    const int col0 = blockIdx.y * 128;
    const int tid  = threadIdx.x;
    const int tx   = tid & 31;
    const int ty   = tid >> 5;

    const int lr  = tid >> 3;
    const int lk4 = (tid & 7) * 4;
    const int grow = row0 + lr;

    const float* Arow = nullptr;
    int ap = 0;
    if (mode == 1) {
        int t = grow >> 6;
        ap = (t == 0) ? 0 : a_idx[grow - 64];
    } else {
        Arow = A + (size_t)grow * K;
    }

    const int cc  = tid >> 1;
    const int kk0 = (tid & 1) * 16;
    const float* Brow0 = B + (size_t)(col0 + cc) * K;

    float acc[4][4];
#pragma unroll
    for (int i = 0; i < 4; i++)
#pragma unroll
        for (int j = 0; j < 4; j++) acc[i][j] = 0.f;

    for (int k0 = 0; k0 < K; k0 += 32) {
        float4 av;
        if (mode == 1) {
            float t4[4];
#pragma unroll
            for (int i = 0; i < 4; i++) {
                int k = k0 + lk4 + i;
                t4[i] = (k < 64) ? cond[(size_t)grow * 64 + k]
                                 : aemb[(size_t)ap * 256 + (k - 64)];
            }
            av = make_float4(t4[0], t4[1], t4[2], t4[3]);
        } else {
            av = *(const float4*)(Arow + k0 + lk4);
        }
        As[lk4 + 0][lr] = av.x; As[lk4 + 1][lr] = av.y;
        As[lk4 + 2][lr] = av.z; As[lk4 + 3][lr] = av.w;

        const float* bp = Brow0 + k0 + kk0;
#pragma unroll
        for (int i = 0; i < 16; i += 4) {
            float4 bv = *(const float4*)(bp + i);
            Bs[kk0 + i + 0][cc] = bv.x; Bs[kk0 + i + 1][cc] = bv.y;
            Bs[kk0 + i + 2][cc] = bv.z; Bs[kk0 + i + 3][cc] = bv.w;
        }
        __syncthreads();

#pragma unroll
        for (int kk = 0; kk < 32; kk++) {
            float4 a = *(const float4*)&As[kk][ty * 4];
            float4 b = *(const float4*)&Bs[kk][tx * 4];
            acc[0][0] += a.x * b.x; acc[0][1] += a.x * b.y; acc[0][2] += a.x * b.z; acc[0][3] += a.x * b.w;
            acc[1][0] += a.y * b.x; acc[1][1] += a.y * b.y; acc[1][2] += a.y * b.z; acc[1][3] += a.y * b.w;
            acc[2][0] += a.z * b.x; acc[2][1] += a.z * b.y; acc[2][2] += a.z * b.z; acc[2][3] += a.z * b.w;
            acc[3][0] += a.w * b.x; acc[3][1] += a.w * b.y; acc[3][2] += a.w * b.z; acc[3][3] += a.w * b.w;
        }
        __syncthreads();
    }

#pragma unroll
    for (int i = 0; i < 4; i++) {
        int row = row0 + ty * 4 + i;
        float4 v = make_float4(acc[i][0], acc[i][1], acc[i][2], acc[i][3]);
        if (bias) {
            int c = col0 + tx * 4;
            v.x += bias[c]; v.y += bias[c + 1]; v.z += bias[c + 2]; v.w += bias[c + 3];
        }
        if (relu) {
            v.x = fmaxf(v.x, 0.f); v.y = fmaxf(v.y, 0.f);
            v.z = fmaxf(v.z, 0.f); v.w = fmaxf(v.w, 0.f);
        }
        *(float4*)(C + (size_t)row * cols + col0 + tx * 4) = v;
    }
}

// ---------------------------------------------------------------------------
// Persistent bidirectional GRU recurrence — EXACT R11 version (993us proven).
// ---------------------------------------------------------------------------
__global__ __launch_bounds__(512, 1)
void recur_kernel(const int* __restrict__ p_idx,
                  const float* __restrict__ bh_f, const float* __restrict__ bh_b)
{
    extern __shared__ char smraw[];
    __half* h16  = (__half*)smraw;                               // 2 x 32*STRH halfs
    float*  sbh  = (float*)(smraw + 2 * 32 * STRH * 2);          // 768 floats
    __half* sXI  = (__half*)(sbh + 768);                         // 16 warps x 16 x STRW halfs
    int*    rrs  = (int*)(sXI + 16 * 16 * STRW);                 // 32 ints

    const int tid  = threadIdx.x;
    const int lane = tid & 31;
    const int w    = tid >> 5;        // 0..15
    const int w8   = w & 7;
    const int mh   = w >> 3;
    const int gr   = lane >> 2;
    const int tig  = lane & 3;

    const int d  = blockIdx.x >> 6;            // direction
    const int c0 = (blockIdx.x & 63) * 32;     // chain base within direction

    const float* bh = d ? bh_b : bh_f;
    for (int i = tid; i < 768; i += 512) sbh[i] = bh[i];
    for (int i = tid; i < 32 * STRH; i += 512) ((uint32_t*)h16)[i] = 0u;  // both buffers
    if (tid < 32) rrs[tid] = p_idx[c0 + tid];

    const uint32_t aoff = (uint32_t)((mh * 16 + (lane & 15)) * STRH * 2 + (lane >> 4) * 16);
    const uint32_t abase0 = smem_u32(h16) + aoff;
    const uint32_t abase1 = smem_u32(h16 + 32 * STRH) + aoff;

    __half* sxw = sXI + w * 16 * STRW;
    const uint32_t sxw_b = smem_u32(sxw);

    const uint4* bb = g_Bh4 + (size_t)d * (96 * 8 * 32);

    float hold[2][4][2];
#pragma unroll
    for (int a = 0; a < 2; a++)
#pragma unroll
        for (int b = 0; b < 4; b++) { hold[a][b][0] = 0.f; hold[a][b][1] = 0.f; }

    __syncthreads();

    for (int j = 0; j < 64; j++) {
#pragma unroll
        for (int it = 0; it < 6; it++) {
            int id   = it * 32 + lane;
            int lrow = id & 15;
            int rem  = id >> 4;
            int gate = rem >> 2;
            int q    = rem & 3;
            int grow = mh * 16 + lrow;
            int rr   = rrs[grow];
            int m    = (d == 0) ? ((j - rr + 64) & 63) : ((63 - j - rr + 128) & 63);
            int n    = (c0 + grow) & 63;
            const __half* src = g_XI16 + ((size_t)d * 4096 + m * 64 + n) * 768
                                + gate * 256 + w8 * 32 + q * 8;
            uint32_t dst = sxw_b + (uint32_t)(lrow * (STRW * 2) + gate * 64 + q * 16);
            asm volatile("cp.async.cg.shared.global [%0], [%1], 16;"
                         :: "r"(dst), "l"(src));
        }
        asm volatile("cp.async.commit_group;");

        const uint32_t abase = (j & 1) ? abase1 : abase0;
        float acc[3][4][4];
#pragma unroll
        for (int g = 0; g < 3; g++)
#pragma unroll
            for (int nt = 0; nt < 4; nt++)
#pragma unroll
                for (int i = 0; i < 4; i++) acc[g][nt][i] = 0.f;

#pragma unroll
        for (int kc2 = 0; kc2 < 8; kc2++) {
            uint32_t a0[4], a1[4];
            {
                uint32_t addr = abase + (uint32_t)(kc2 * 64);
                asm volatile("ldmatrix.sync.aligned.m8n8.x4.shared.b16 {%0,%1,%2,%3}, [%4];"
                             : "=r"(a0[0]), "=r"(a0[1]), "=r"(a0[2]), "=r"(a0[3]) : "r"(addr));
                asm volatile("ldmatrix.sync.aligned.m8n8.x4.shared.b16 {%0,%1,%2,%3}, [%4];"
                             : "=r"(a1[0]), "=r"(a1[1]), "=r"(a1[2]), "=r"(a1[3]) : "r"(addr + 32));
            }
#pragma unroll
            for (int g = 0; g < 3; g++) {
                uint4 bv[4];
#pragma unroll
                for (int nt = 0; nt < 4; nt++)
                    bv[nt] = __ldg(bb + ((size_t)((g * 32 + w8 * 4 + nt) * 8 + kc2)) * 32 + lane);
#pragma unroll
                for (int nt = 0; nt < 4; nt++) {
                    mma_f16(acc[g][nt], a0[0], a0[1], a0[2], a0[3], bv[nt].x, bv[nt].y);
                    mma_f16(acc[g][nt], a1[0], a1[1], a1[2], a1[3], bv[nt].z, bv[nt].w);
                }
            }
        }

        asm volatile("cp.async.wait_group 0;" ::: "memory");
        __syncwarp();

        __half* hnext = h16 + ((j & 1) ^ 1) * (32 * STRH);
#pragma unroll
        for (int nt = 0; nt < 4; nt++) {
            const int lcol = nt * 8 + 2 * tig;
            const int colb = w8 * 32 + lcol;
#pragma unroll
            for (int rw = 0; rw < 2; rw++) {
                const int lrow = rw * 8 + gr;
                const int row  = mh * 16 + lrow;
                const __half* xr = sxw + lrow * STRW + lcol;
                float2 xir = __half22float2(*(const __half2*)(xr));
                float2 xiz = __half22float2(*(const __half2*)(xr + 32));
                float2 xin = __half22float2(*(const __half2*)(xr + 64));

                float ghr0 = acc[0][nt][rw * 2 + 0] + sbh[colb];
                float ghr1 = acc[0][nt][rw * 2 + 1] + sbh[colb + 1];
                float ghz0 = acc[1][nt][rw * 2 + 0] + sbh[256 + colb];
                float ghz1 = acc[1][nt][rw * 2 + 1] + sbh[256 + colb + 1];
                float ghn0 = acc[2][nt][rw * 2 + 0] + sbh[512 + colb];
                float ghn1 = acc[2][nt][rw * 2 + 1] + sbh[512 + colb + 1];

                float r0 = __fdividef(1.f, 1.f + __expf(-(xir.x + ghr0)));
                float r1 = __fdividef(1.f, 1.f + __expf(-(xir.y + ghr1)));
                float z0 = __fdividef(1.f, 1.f + __expf(-(xiz.x + ghz0)));
                float z1 = __fdividef(1.f, 1.f + __expf(-(xiz.y + ghz1)));
                float n0, n1;
                asm("tanh.approx.f32 %0, %1;" : "=f"(n0) : "f"(xin.x + r0 * ghn0));
                asm("tanh.approx.f32 %0, %1;" : "=f"(n1) : "f"(xin.y + r1 * ghn1));

                float h0 = (1.f - z0) * n0 + z0 * hold[rw][nt][0];
                float h1 = (1.f - z1) * n1 + z1 * hold[rw][nt][1];
                hold[rw][nt][0] = h0;
                hold[rw][nt][1] = h1;

                __half2 hh = __floats2half2_rn(h0, h1);
                *(__half2*)&hnext[row * STRH + colb] = hh;
                *(__half2*)(g_K16 + ((((size_t)(c0 + row)) * 2 + d) * 64 + j) * 256 + colb) = hh;
            }
        }
        __syncthreads();
    }
}

// ---------------------------------------------------------------------------
// matvec: fp32 weights, float4 loads (8 warps)
// ---------------------------------------------------------------------------
__device__ __forceinline__ void matvec8(float* __restrict__ y,
                                        const float* __restrict__ W,
                                        const float* __restrict__ b,
                                        const float* __restrict__ x,
                                        int Nout, int K)
{
    int tid  = threadIdx.x;
    int lane = tid & 31, warp = tid >> 5;
    int s = lane & 7, og = lane >> 3;
    for (int ob = warp * 4; ob < Nout; ob += 32) {
        int o = ob + og;
        bool valid = (o < Nout);
        const float* w = W + (size_t)(valid ? o : ob) * K;
        float acc = 0.f;
        for (int k = s * 4; k < K; k += 32) {
            float4 wv = *(const float4*)(w + k);
            float4 xv = *(const float4*)(x + k);
            acc += wv.x * xv.x + wv.y * xv.y + wv.z * xv.z + wv.w * xv.w;
        }
        acc += __shfl_down_sync(0xffffffffu, acc, 4);
        acc += __shfl_down_sync(0xffffffffu, acc, 2);
        acc += __shfl_down_sync(0xffffffffu, acc, 1);
        if (s == 0 && valid) y[o] = b ? (acc + b[o]) : acc;
    }
}

// ---------------------------------------------------------------------------
// matvec: fp16 weights, LDG.128, K=256, NW warps
// ---------------------------------------------------------------------------
template <int NW>
__device__ __forceinline__ void matvec8h16(float* __restrict__ y,
                                           const __half* __restrict__ W,
                                           const float* __restrict__ b,
                                           const float* __restrict__ x,
                                           int Nout)
{
    int tid  = threadIdx.x;
    int lane = tid & 31, warp = tid >> 5;
    int s = lane & 7, og = lane >> 3;
    for (int ob = warp * 4; ob < Nout; ob += NW * 4) {
        int o = ob + og;
        bool valid = (o < Nout);
        const uint4* w4 = (const uint4*)(W + (size_t)(valid ? o : ob) * 256);
        float acc = 0.f;
#pragma unroll
        for (int it = 0; it < 4; it++) {
            int k = s * 8 + it * 64;
            uint4 wv = __ldg(w4 + (k >> 3));
            const __half2* hp = (const __half2*)&wv;
            float4 xa = *(const float4*)(x + k);
            float4 xb = *(const float4*)(x + k + 4);
            float2 w0 = __half22float2(hp[0]);
            float2 w1 = __half22float2(hp[1]);
            float2 w2 = __half22float2(hp[2]);
            float2 w3 = __half22float2(hp[3]);
            acc += w0.x * xa.x + w0.y * xa.y + w1.x * xa.z + w1.y * xa.w
                 + w2.x * xb.x + w2.y * xb.y + w3.x * xb.z + w3.y * xb.w;
        }
        acc += __shfl_down_sync(0xffffffffu, acc, 4);
        acc += __shfl_down_sync(0xffffffffu, acc, 2);
        acc += __shfl_down_sync(0xffffffffu, acc, 1);
        if (s == 0 && valid) y[o] = b ? (acc + b[o]) : acc;
    }
}

// ---------------------------------------------------------------------------
// D1: decoder h-recurrence ONLY — EXACT R11 version. 64 blocks x 512 threads.
// ---------------------------------------------------------------------------
__global__ __launch_bounds__(512)
void decoder_h(const float* __restrict__ cell_bh)
{
    const int n = blockIdx.x;
    const int tid = threadIdx.x;

    __shared__ float sh_h[256];
    __shared__ float sh_gh[768];

    if (tid < 256) sh_h[tid] = 0.f;
    __syncthreads();

    for (int t = 0; t < T_; t++) {
        matvec8h16<16>(sh_gh, g_Wc16, cell_bh, sh_h, 768);
        __syncthreads();

        if (tid < 256) {
            const float* gi = g_GI + (size_t)(t * 64 + n) * 768;
            float h_old = sh_h[tid];
            float rg = 1.f / (1.f + __expf(-(gi[tid]       + sh_gh[tid])));
            float zg = 1.f / (1.f + __expf(-(gi[256 + tid] + sh_gh[256 + tid])));
            float tn;
            asm("tanh.approx.f32 %0, %1;" : "=f"(tn) : "f"(gi[512 + tid] + rg * sh_gh[512 + tid]));
            float hnew = (1.f - zg) * tn + zg * h_old;
            sh_h[tid] = hnew;
            g_H2[(size_t)(t * 64 + n) * 256 + tid] = hnew;
        }
        __syncthreads();
    }
}

// ---------------------------------------------------------------------------
// D2: heads + SINGLE-PASS attention. One block per (t,n), 256 threads.
// Warp w owns K rows [w*16, w*16+16). Per row: one LDG.128/lane (8 halfs),
// row-dot with q via warp shuffle-reduce, immediate zz accumulation in regs.
// K is read from global exactly ONCE (was twice).
// ---------------------------------------------------------------------------
__global__ __launch_bounds__(256)
void decoder_heads(const float* __restrict__ pointer_w, const float* __restrict__ pointer_b,
                   const float* __restrict__ actor_w, const float* __restrict__ actor_b,
                   const float* __restrict__ critic_w, const float* __restrict__ critic_b,
                   const int* __restrict__ a_idx, const int* __restrict__ p_idx,
                   float* __restrict__ out)
{
    const int tn = blockIdx.x;            // t*64 + n
    const int tid = threadIdx.x;
    const int lane = tid & 31;
    const int w    = tid >> 5;

    __shared__ float sh_h[256];
    __shared__ float sh_q[256];
    __shared__ float szz[8 * 256];        // per-warp zz partials
    __shared__ float sh_zz[256];
    __shared__ float sh_pl[64];
    __shared__ float sh_al[16];
    __shared__ float sh_v[4];
    __shared__ float s_max, s_sum;

    sh_h[tid] = g_H2[(size_t)tn * 256 + tid];
    sh_q[tid] = g_Q [(size_t)tn * 256 + tid];
    __syncthreads();

    matvec8(sh_pl, pointer_w, pointer_b, sh_h, 64, 256);
    matvec8(sh_v,  critic_w,  critic_b,  sh_h, 1, 256);

    // ---- single-pass attention over this chain's 128 keys
    const __half* Kc = g_K16 + (size_t)tn * (2 * 64 * 256);   // [128][256] fp16
    {
        float qv[8];
        const float* qp = sh_q + lane * 8;
#pragma unroll
        for (int j2 = 0; j2 < 8; j2++) qv[j2] = qp[j2];

        float zzl[8];
#pragma unroll
        for (int j2 = 0; j2 < 8; j2++) zzl[j2] = 0.f;

#pragma unroll 4
        for (int r = 0; r < 16; r++) {
            int k = w * 16 + r;
            uint4 kv = __ldg((const uint4*)(Kc + (size_t)k * 256 + lane * 8));
            const __half2* hp = (const __half2*)&kv;
            float kf[8];
#pragma unroll
            for (int p = 0; p < 4; p++) {
                float2 f = __half22float2(hp[p]);
                kf[2 * p]     = f.x;
                kf[2 * p + 1] = f.y;
            }
            float part = 0.f;
#pragma unroll
            for (int j2 = 0; j2 < 8; j2++) part += kf[j2] * qv[j2];
#pragma unroll
            for (int o = 16; o > 0; o >>= 1)
                part += __shfl_xor_sync(0xffffffffu, part, o);
            // part == l_k on all lanes
#pragma unroll
            for (int j2 = 0; j2 < 8; j2++) zzl[j2] += part * kf[j2];
        }
#pragma unroll
        for (int j2 = 0; j2 < 8; j2++) szz[w * 256 + lane * 8 + j2] = zzl[j2];
    }
    __syncthreads();

    // pointer softmax (64)
    if (tid < 32) {
        float m = fmaxf(sh_pl[tid], sh_pl[tid + 32]);
#pragma unroll
        for (int o = 16; o > 0; o >>= 1) m = fmaxf(m, __shfl_xor_sync(0xffffffffu, m, o));
        if (tid == 0) s_max = m;
    }
    __syncthreads();
    if (tid < 64) sh_pl[tid] = __expf(sh_pl[tid] - s_max);
    __syncthreads();
    if (tid < 32) {
        float s = sh_pl[tid] + sh_pl[tid + 32];
#pragma unroll
        for (int o = 16; o > 0; o >>= 1) s += __shfl_xor_sync(0xffffffffu, s, o);
        if (tid == 0) s_sum = s;
    }

    // reduce zz partials across warps
    {
        float acc = 0.f;
#pragma unroll
        for (int w2 = 0; w2 < 8; w2++) acc += szz[w2 * 256 + tid];
        sh_zz[tid] = acc;
    }
    __syncthreads();

    matvec8(sh_al, actor_w, actor_b, sh_zz, 16, 256);
    __syncthreads();
    if (tid < 32) {
        float v = (tid < 16) ? sh_al[tid] : -1e30f;
        float m = v;
#pragma unroll
        for (int o = 16; o > 0; o >>= 1) m = fmaxf(m, __shfl_xor_sync(0xffffffffu, m, o));
        float e = (tid < 16) ? __expf(v - m) : 0.f;
        float s = e;
#pragma unroll
        for (int o = 16; o > 0; o >>= 1) s += __shfl_xor_sync(0xffffffffu, s, o);
        if (tid < 16) sh_al[tid] = e / s;
    }
    __syncthreads();

    float* orow = out + (size_t)tn * 339;
    if (tid == 0) {
        orow[0] = (float)a_idx[tn];
        orow[1] = (float)p_idx[tn];
        orow[2] = sh_v[0];
    }
    orow[3 + tid] = sh_h[tid];
    if (tid < 16) orow[259 + tid] = sh_al[tid];
    if (tid < 64) orow[275 + tid] = sh_pl[tid] / s_sum;
}

// ---------------------------------------------------------------------------
// Launch — EXACT R11 structure (993us proven). ONE change: decoder_heads
// uses single-pass attention.
// ---------------------------------------------------------------------------
extern "C" void kernel_launch(void* const* d_in, const int* in_sizes, int n_in,
                              void* d_out, int out_size)
{
    const float* condition = (const float*)d_in[0];
    const int*   lines     = (const int*)  d_in[1];
    const int*   a_idx     = (const int*)  d_in[2];
    const int*   p_idx     = (const int*)  d_in[3];
    const float* embed     = (const float*)d_in[4];
    const float* aemb      = (const float*)d_in[5];
    const float* gru_wi_f  = (const float*)d_in[6];
    const float* gru_wh_f  = (const float*)d_in[7];
    const float* gru_bi_f  = (const float*)d_in[8];
    const float* gru_bh_f  = (const float*)d_in[9];
    const float* gru_wi_b  = (const float*)d_in[10];
    const float* gru_wh_b  = (const float*)d_in[11];
    const float* gru_bi_b  = (const float*)d_in[12];
    const float* gru_bh_b  = (const float*)d_in[13];
    const float* f_w1      = (const float*)d_in[14];
    const float* f_b1      = (const float*)d_in[15];
    const float* f_w2      = (const float*)d_in[16];
    const float* f_b2      = (const float*)d_in[17];
    const float* cell_wi   = (const float*)d_in[18];
    const float* cell_wh   = (const float*)d_in[19];
    const float* cell_bi   = (const float*)d_in[20];
    const float* cell_bh   = (const float*)d_in[21];
    const float* critic_w  = (const float*)d_in[22];
    const float* critic_b  = (const float*)d_in[23];
    const float* pointer_w = (const float*)d_in[24];
    const float* pointer_b = (const float*)d_in[25];
    const float* actor_w   = (const float*)d_in[26];
    const float* actor_b   = (const float*)d_in[27];
    const float* query_w   = (const float*)d_in[28];
    const float* query_b   = (const float*)d_in[29];
    float* out = (float*)d_out;

    void *pXF1_, *pXF2_, *pGI_, *pH2_, *pQ_;
    cudaGetSymbolAddress(&pXF1_, g_XF1);
    cudaGetSymbolAddress(&pXF2_, g_XF2);
    cudaGetSymbolAddress(&pGI_,  g_GI);
    cudaGetSymbolAddress(&pH2_,  g_H2);
    cudaGetSymbolAddress(&pQ_,   g_Q);
    float* pXF1 = (float*)pXF1_;
    float* pXF2 = (float*)pXF2_;
    float* pGI  = (float*)pGI_;
    float* pH2  = (float*)pH2_;
    float* pQ   = (float*)pQ_;

    const int SMEM_REC = 2 * 32 * STRH * 2 + 768 * 4 + 16 * 16 * STRW * 2 + 32 * 4;
    cudaFuncSetAttribute(recur_kernel, cudaFuncAttributeMaxDynamicSharedMemorySize, SMEM_REC);

    // 0) weight permutes / conversions (R11 order)
    permute_w16<<<384, 256>>>(gru_wh_f, gru_wh_b, gru_wi_f, gru_wi_b);
    cvt_cellwh<<<768, 256>>>(cell_wh);

    // 1) XI projections via fp16 MMA
    xi_mma<<<256, 512>>>(lines, embed, gru_bi_f, gru_bi_b);

    // 2) decoder MLP + cell input gates (fp32)
    gemm_k<<<dim3(64, 2), 256>>>(1, nullptr, f_w1, f_b1, pXF1,
                                 256, 320, 1, condition, aemb, a_idx);
    gemm_k<<<dim3(64, 2), 256>>>(2, pXF1, f_w2, f_b2, pXF2,
                                 256, 256, 1, nullptr, nullptr, nullptr);
    gemm_k<<<dim3(64, 6), 256>>>(2, pXF2, cell_wi, cell_bi, pGI,
                                 768, 256, 0, nullptr, nullptr, nullptr);

    // 3) persistent fp16-MMA recurrence (R11, untouched)
    recur_kernel<<<128, 512, SMEM_REC>>>(p_idx, gru_bh_f, gru_bh_b);

    // 4) decoder: h-chain (R11), batched q GEMM, single-pass heads
    decoder_h<<<64, 512>>>(cell_bh);
    gemm_k<<<dim3(64, 2), 256>>>(2, pH2, query_w, query_b, pQ,
                                 256, 256, 0, nullptr, nullptr, nullptr);
    decoder_heads<<<2048, 256>>>(pointer_w, pointer_b, actor_w, actor_b,
                                 critic_w, critic_b, a_idx, p_idx, out);
}

// round 17
// speedup vs baseline: 1.9152x; 1.1727x over previous
#include <cuda_runtime.h>
#include <cuda_fp16.h>
#include <math.h>
#include <stdint.h>

// Problem constants
#define T_  32
#define N_  64
#define H_  256

#define STRH 264    // h16 smem row stride (halfs)
#define STRW 104    // per-warp XI slice row stride (halfs): 96 + 8 pad

// ---------------------------------------------------------------------------
// Device scratch
// ---------------------------------------------------------------------------
__device__ __half g_XI16[2ull * 4096 * 768];        // [dir][m*64+n][3H] fp16
__device__ float  g_XF1[2048ull * 256];
__device__ float  g_XF2[2048ull * 256];
__device__ __half g_GI16[2048ull * 768];            // cell gi fp16 (bias folded)
__device__ __half g_K16[2048ull * 2 * 64 * 256];    // GRU outputs fp16
__device__ uint4  g_Bh4[5ull * 96 * 8 * 32];        // fp16 B-fragments: whf, whb, wif, wib, cellwh
__device__ float  g_H2 [2048ull * 256];             // decoder h per (t,n) fp32
__device__ float  g_Q  [2048ull * 256];             // decoder q per (t,n) fp32

// ---------------------------------------------------------------------------
// helpers
// ---------------------------------------------------------------------------
__device__ __forceinline__ uint32_t packh2(float a, float b) {
    __half2 h = __floats2half2_rn(a, b);
    return *(uint32_t*)&h;
}

__device__ __forceinline__ void mma_f16(float* c, uint32_t a0, uint32_t a1, uint32_t a2,
                                        uint32_t a3, uint32_t b0, uint32_t b1) {
    asm volatile(
        "mma.sync.aligned.m16n8k16.row.col.f32.f16.f16.f32 "
        "{%0,%1,%2,%3}, {%4,%5,%6,%7}, {%8,%9}, {%0,%1,%2,%3};"
        : "+f"(c[0]), "+f"(c[1]), "+f"(c[2]), "+f"(c[3])
        : "r"(a0), "r"(a1), "r"(a2), "r"(a3), "r"(b0), "r"(b1));
}

__device__ __forceinline__ uint32_t smem_u32(const void* p) {
    return (uint32_t)__cvta_generic_to_shared(p);
}

// ---------------------------------------------------------------------------
// Permute five [768,256] weights into fp16 B-fragment order.
// Slices: 0=gru_wh_f, 1=gru_wh_b, 2=gru_wi_f, 3=gru_wi_b, 4=cell_wh.
// ---------------------------------------------------------------------------
__global__ __launch_bounds__(256)
void permute_w16(const float* __restrict__ whf, const float* __restrict__ whb,
                 const float* __restrict__ wif, const float* __restrict__ wib,
                 const float* __restrict__ cwh) {
    int idx = blockIdx.x * 256 + threadIdx.x;
    if (idx >= 5 * 96 * 8 * 32) return;
    int widx = idx / 24576;
    int r    = idx % 24576;
    int lane = r & 31;
    int kc2  = (r >> 5) & 7;
    int nt   = r >> 8;                       // 0..95
    int gr = lane >> 2, tig = lane & 3;
    const float* W = (widx == 0) ? whf : (widx == 1) ? whb :
                     (widx == 2) ? wif : (widx == 3) ? wib : cwh;
    const float* wr = W + (size_t)(nt * 8 + gr) * 256 + kc2 * 32 + 2 * tig;
    uint4 o;
    o.x = packh2(wr[0],  wr[1]);
    o.y = packh2(wr[8],  wr[9]);
    o.z = packh2(wr[16], wr[17]);
    o.w = packh2(wr[24], wr[25]);
    g_Bh4[idx] = o;
}

// ---------------------------------------------------------------------------
// XI projection via fp16 MMA (validated): XI = embed[lines] @ Wi^T + bi.
// ---------------------------------------------------------------------------
__global__ __launch_bounds__(512, 1)
void xi_mma(const int* __restrict__ lines, const float* __restrict__ embed,
            const float* __restrict__ bi_f, const float* __restrict__ bi_b)
{
    __shared__ __half a16[32 * STRH];
    __shared__ float  sbi[768];

    const int tid  = threadIdx.x;
    const int lane = tid & 31;
    const int w    = tid >> 5;
    const int w8   = w & 7;
    const int mh   = w >> 3;
    const int gr   = lane >> 2;
    const int tig  = lane & 3;

    const int d  = blockIdx.x >> 7;
    const int r0 = (blockIdx.x & 127) * 32;

    const float* bi = d ? bi_b : bi_f;
    for (int i = tid; i < 768; i += 512) sbi[i] = bi[i];

#pragma unroll
    for (int rw2 = 0; rw2 < 2; rw2++) {
        int row  = w * 2 + rw2;
        int grow = r0 + row;
        int m = grow >> 6, n = grow & 63;
        const float* src = embed + (size_t)lines[n * 64 + m] * 256 + lane * 8;
        float4 v0 = *(const float4*)(src);
        float4 v1 = *(const float4*)(src + 4);
        __half2* dst = (__half2*)&a16[row * STRH + lane * 8];
        dst[0] = __floats2half2_rn(v0.x, v0.y);
        dst[1] = __floats2half2_rn(v0.z, v0.w);
        dst[2] = __floats2half2_rn(v1.x, v1.y);
        dst[3] = __floats2half2_rn(v1.z, v1.w);
    }
    __syncthreads();

    const uint32_t abase = smem_u32(a16) + (uint32_t)((mh * 16 + (lane & 15)) * STRH * 2
                                                      + (lane >> 4) * 16);
    const uint4* bb = g_Bh4 + (size_t)(2 + d) * (96 * 8 * 32);

    float acc[3][4][4];
#pragma unroll
    for (int g = 0; g < 3; g++)
#pragma unroll
        for (int nt = 0; nt < 4; nt++)
#pragma unroll
            for (int i = 0; i < 4; i++) acc[g][nt][i] = 0.f;

#pragma unroll
    for (int kc2 = 0; kc2 < 8; kc2++) {
        uint32_t a0[4], a1[4];
        uint32_t addr = abase + (uint32_t)(kc2 * 64);
        asm volatile("ldmatrix.sync.aligned.m8n8.x4.shared.b16 {%0,%1,%2,%3}, [%4];"
                     : "=r"(a0[0]), "=r"(a0[1]), "=r"(a0[2]), "=r"(a0[3]) : "r"(addr));
        asm volatile("ldmatrix.sync.aligned.m8n8.x4.shared.b16 {%0,%1,%2,%3}, [%4];"
                     : "=r"(a1[0]), "=r"(a1[1]), "=r"(a1[2]), "=r"(a1[3]) : "r"(addr + 32));
#pragma unroll
        for (int g = 0; g < 3; g++) {
            uint4 bv[4];
#pragma unroll
            for (int nt = 0; nt < 4; nt++)
                bv[nt] = __ldg(bb + ((size_t)((g * 32 + w8 * 4 + nt) * 8 + kc2)) * 32 + lane);
#pragma unroll
            for (int nt = 0; nt < 4; nt++) {
                mma_f16(acc[g][nt], a0[0], a0[1], a0[2], a0[3], bv[nt].x, bv[nt].y);
                mma_f16(acc[g][nt], a1[0], a1[1], a1[2], a1[3], bv[nt].z, bv[nt].w);
            }
        }
    }

    __half* xout = g_XI16 + (size_t)d * (4096ull * 768);
#pragma unroll
    for (int g = 0; g < 3; g++)
#pragma unroll
        for (int nt = 0; nt < 4; nt++) {
            const int colb = w8 * 32 + nt * 8 + 2 * tig;
#pragma unroll
            for (int rw = 0; rw < 2; rw++) {
                const int row = mh * 16 + rw * 8 + gr;
                float v0 = acc[g][nt][rw * 2 + 0] + sbi[g * 256 + colb];
                float v1 = acc[g][nt][rw * 2 + 1] + sbi[g * 256 + colb + 1];
                *(__half2*)(xout + (size_t)(r0 + row) * 768 + g * 256 + colb)
                    = __floats2half2_rn(v0, v1);
            }
        }
}

// ---------------------------------------------------------------------------
// Generic tiled fp32 GEMM (setup); outHalf stores fp16
// ---------------------------------------------------------------------------
__global__ __launch_bounds__(256)
void gemm_k(int mode, const float* __restrict__ A, const float* __restrict__ B,
            const float* __restrict__ bias, float* __restrict__ C,
            int cols, int K, int relu, int outHalf,
            const float* __restrict__ cond, const float* __restrict__ aemb,
            const int* __restrict__ a_idx)
{
    __shared__ float As[32][36];
    __shared__ float Bs[32][132];

    const int row0 = blockIdx.x * 32;
    const int col0 = blockIdx.y * 128;
    const int tid  = threadIdx.x;
    const int tx   = tid & 31;
    const int ty   = tid >> 5;

    const int lr  = tid >> 3;
    const int lk4 = (tid & 7) * 4;
    const int grow = row0 + lr;

    const float* Arow = nullptr;
    int ap = 0;
    if (mode == 1) {
        int t = grow >> 6;
        ap = (t == 0) ? 0 : a_idx[grow - 64];
    } else {
        Arow = A + (size_t)grow * K;
    }

    const int cc  = tid >> 1;
    const int kk0 = (tid & 1) * 16;
    const float* Brow0 = B + (size_t)(col0 + cc) * K;

    float acc[4][4];
#pragma unroll
    for (int i = 0; i < 4; i++)
#pragma unroll
        for (int j = 0; j < 4; j++) acc[i][j] = 0.f;

    for (int k0 = 0; k0 < K; k0 += 32) {
        float4 av;
        if (mode == 1) {
            float t4[4];
#pragma unroll
            for (int i = 0; i < 4; i++) {
                int k = k0 + lk4 + i;
                t4[i] = (k < 64) ? cond[(size_t)grow * 64 + k]
                                 : aemb[(size_t)ap * 256 + (k - 64)];
            }
            av = make_float4(t4[0], t4[1], t4[2], t4[3]);
        } else {
            av = *(const float4*)(Arow + k0 + lk4);
        }
        As[lk4 + 0][lr] = av.x; As[lk4 + 1][lr] = av.y;
        As[lk4 + 2][lr] = av.z; As[lk4 + 3][lr] = av.w;

        const float* bp = Brow0 + k0 + kk0;
#pragma unroll
        for (int i = 0; i < 16; i += 4) {
            float4 bv = *(const float4*)(bp + i);
            Bs[kk0 + i + 0][cc] = bv.x; Bs[kk0 + i + 1][cc] = bv.y;
            Bs[kk0 + i + 2][cc] = bv.z; Bs[kk0 + i + 3][cc] = bv.w;
        }
        __syncthreads();

#pragma unroll
        for (int kk = 0; kk < 32; kk++) {
            float4 a = *(const float4*)&As[kk][ty * 4];
            float4 b = *(const float4*)&Bs[kk][tx * 4];
            acc[0][0] += a.x * b.x; acc[0][1] += a.x * b.y; acc[0][2] += a.x * b.z; acc[0][3] += a.x * b.w;
            acc[1][0] += a.y * b.x; acc[1][1] += a.y * b.y; acc[1][2] += a.y * b.z; acc[1][3] += a.y * b.w;
            acc[2][0] += a.z * b.x; acc[2][1] += a.z * b.y; acc[2][2] += a.z * b.z; acc[2][3] += a.z * b.w;
            acc[3][0] += a.w * b.x; acc[3][1] += a.w * b.y; acc[3][2] += a.w * b.z; acc[3][3] += a.w * b.w;
        }
        __syncthreads();
    }

#pragma unroll
    for (int i = 0; i < 4; i++) {
        int row = row0 + ty * 4 + i;
        float4 v = make_float4(acc[i][0], acc[i][1], acc[i][2], acc[i][3]);
        if (bias) {
            int c = col0 + tx * 4;
            v.x += bias[c]; v.y += bias[c + 1]; v.z += bias[c + 2]; v.w += bias[c + 3];
        }
        if (relu) {
            v.x = fmaxf(v.x, 0.f); v.y = fmaxf(v.y, 0.f);
            v.z = fmaxf(v.z, 0.f); v.w = fmaxf(v.w, 0.f);
        }
        if (outHalf) {
            __half* Ch = (__half*)C;
            __half2* dst = (__half2*)(Ch + (size_t)row * cols + col0 + tx * 4);
            dst[0] = __floats2half2_rn(v.x, v.y);
            dst[1] = __floats2half2_rn(v.z, v.w);
        } else {
            *(float4*)(C + (size_t)row * cols + col0 + tx * 4) = v;
        }
    }
}

// ---------------------------------------------------------------------------
// Persistent bidirectional GRU recurrence — EXACT R11 version (proven).
// ---------------------------------------------------------------------------
__global__ __launch_bounds__(512, 1)
void recur_kernel(const int* __restrict__ p_idx,
                  const float* __restrict__ bh_f, const float* __restrict__ bh_b)
{
    extern __shared__ char smraw[];
    __half* h16  = (__half*)smraw;                               // 2 x 32*STRH halfs
    float*  sbh  = (float*)(smraw + 2 * 32 * STRH * 2);          // 768 floats
    __half* sXI  = (__half*)(sbh + 768);                         // 16 warps x 16 x STRW halfs
    int*    rrs  = (int*)(sXI + 16 * 16 * STRW);                 // 32 ints

    const int tid  = threadIdx.x;
    const int lane = tid & 31;
    const int w    = tid >> 5;        // 0..15
    const int w8   = w & 7;
    const int mh   = w >> 3;
    const int gr   = lane >> 2;
    const int tig  = lane & 3;

    const int d  = blockIdx.x >> 6;            // direction
    const int c0 = (blockIdx.x & 63) * 32;     // chain base within direction

    const float* bh = d ? bh_b : bh_f;
    for (int i = tid; i < 768; i += 512) sbh[i] = bh[i];
    for (int i = tid; i < 32 * STRH; i += 512) ((uint32_t*)h16)[i] = 0u;  // both buffers
    if (tid < 32) rrs[tid] = p_idx[c0 + tid];

    const uint32_t aoff = (uint32_t)((mh * 16 + (lane & 15)) * STRH * 2 + (lane >> 4) * 16);
    const uint32_t abase0 = smem_u32(h16) + aoff;
    const uint32_t abase1 = smem_u32(h16 + 32 * STRH) + aoff;

    __half* sxw = sXI + w * 16 * STRW;
    const uint32_t sxw_b = smem_u32(sxw);

    const uint4* bb = g_Bh4 + (size_t)d * (96 * 8 * 32);

    float hold[2][4][2];
#pragma unroll
    for (int a = 0; a < 2; a++)
#pragma unroll
        for (int b = 0; b < 4; b++) { hold[a][b][0] = 0.f; hold[a][b][1] = 0.f; }

    __syncthreads();

    for (int j = 0; j < 64; j++) {
#pragma unroll
        for (int it = 0; it < 6; it++) {
            int id   = it * 32 + lane;
            int lrow = id & 15;
            int rem  = id >> 4;
            int gate = rem >> 2;
            int q    = rem & 3;
            int grow = mh * 16 + lrow;
            int rr   = rrs[grow];
            int m    = (d == 0) ? ((j - rr + 64) & 63) : ((63 - j - rr + 128) & 63);
            int n    = (c0 + grow) & 63;
            const __half* src = g_XI16 + ((size_t)d * 4096 + m * 64 + n) * 768
                                + gate * 256 + w8 * 32 + q * 8;
            uint32_t dst = sxw_b + (uint32_t)(lrow * (STRW * 2) + gate * 64 + q * 16);
            asm volatile("cp.async.cg.shared.global [%0], [%1], 16;"
                         :: "r"(dst), "l"(src));
        }
        asm volatile("cp.async.commit_group;");

        const uint32_t abase = (j & 1) ? abase1 : abase0;
        float acc[3][4][4];
#pragma unroll
        for (int g = 0; g < 3; g++)
#pragma unroll
            for (int nt = 0; nt < 4; nt++)
#pragma unroll
                for (int i = 0; i < 4; i++) acc[g][nt][i] = 0.f;

#pragma unroll
        for (int kc2 = 0; kc2 < 8; kc2++) {
            uint32_t a0[4], a1[4];
            {
                uint32_t addr = abase + (uint32_t)(kc2 * 64);
                asm volatile("ldmatrix.sync.aligned.m8n8.x4.shared.b16 {%0,%1,%2,%3}, [%4];"
                             : "=r"(a0[0]), "=r"(a0[1]), "=r"(a0[2]), "=r"(a0[3]) : "r"(addr));
                asm volatile("ldmatrix.sync.aligned.m8n8.x4.shared.b16 {%0,%1,%2,%3}, [%4];"
                             : "=r"(a1[0]), "=r"(a1[1]), "=r"(a1[2]), "=r"(a1[3]) : "r"(addr + 32));
            }
#pragma unroll
            for (int g = 0; g < 3; g++) {
                uint4 bv[4];
#pragma unroll
                for (int nt = 0; nt < 4; nt++)
                    bv[nt] = __ldg(bb + ((size_t)((g * 32 + w8 * 4 + nt) * 8 + kc2)) * 32 + lane);
#pragma unroll
                for (int nt = 0; nt < 4; nt++) {
                    mma_f16(acc[g][nt], a0[0], a0[1], a0[2], a0[3], bv[nt].x, bv[nt].y);
                    mma_f16(acc[g][nt], a1[0], a1[1], a1[2], a1[3], bv[nt].z, bv[nt].w);
                }
            }
        }

        asm volatile("cp.async.wait_group 0;" ::: "memory");
        __syncwarp();

        __half* hnext = h16 + ((j & 1) ^ 1) * (32 * STRH);
#pragma unroll
        for (int nt = 0; nt < 4; nt++) {
            const int lcol = nt * 8 + 2 * tig;
            const int colb = w8 * 32 + lcol;
#pragma unroll
            for (int rw = 0; rw < 2; rw++) {
                const int lrow = rw * 8 + gr;
                const int row  = mh * 16 + lrow;
                const __half* xr = sxw + lrow * STRW + lcol;
                float2 xir = __half22float2(*(const __half2*)(xr));
                float2 xiz = __half22float2(*(const __half2*)(xr + 32));
                float2 xin = __half22float2(*(const __half2*)(xr + 64));

                float ghr0 = acc[0][nt][rw * 2 + 0] + sbh[colb];
                float ghr1 = acc[0][nt][rw * 2 + 1] + sbh[colb + 1];
                float ghz0 = acc[1][nt][rw * 2 + 0] + sbh[256 + colb];
                float ghz1 = acc[1][nt][rw * 2 + 1] + sbh[256 + colb + 1];
                float ghn0 = acc[2][nt][rw * 2 + 0] + sbh[512 + colb];
                float ghn1 = acc[2][nt][rw * 2 + 1] + sbh[512 + colb + 1];

                float r0 = __fdividef(1.f, 1.f + __expf(-(xir.x + ghr0)));
                float r1 = __fdividef(1.f, 1.f + __expf(-(xir.y + ghr1)));
                float z0 = __fdividef(1.f, 1.f + __expf(-(xiz.x + ghz0)));
                float z1 = __fdividef(1.f, 1.f + __expf(-(xiz.y + ghz1)));
                float n0, n1;
                asm("tanh.approx.f32 %0, %1;" : "=f"(n0) : "f"(xin.x + r0 * ghn0));
                asm("tanh.approx.f32 %0, %1;" : "=f"(n1) : "f"(xin.y + r1 * ghn1));

                float h0 = (1.f - z0) * n0 + z0 * hold[rw][nt][0];
                float h1 = (1.f - z1) * n1 + z1 * hold[rw][nt][1];
                hold[rw][nt][0] = h0;
                hold[rw][nt][1] = h1;

                __half2 hh = __floats2half2_rn(h0, h1);
                *(__half2*)&hnext[row * STRH + colb] = hh;
                *(__half2*)(g_K16 + ((((size_t)(c0 + row)) * 2 + d) * 64 + j) * 256 + colb) = hh;
            }
        }
        __syncthreads();
    }
}

// ---------------------------------------------------------------------------
// Decoder h-chain via fp16 MMA (recur template, no roll). 2 blocks x 512 thr,
// 32 chains each, 32 steps. gi = g_GI16 (fp16, bias folded). h -> g_H2 fp32.
// ---------------------------------------------------------------------------
__global__ __launch_bounds__(512, 1)
void decoder_h_mma(const float* __restrict__ cell_bh)
{
    extern __shared__ char smraw[];
    __half* h16  = (__half*)smraw;                               // 2 x 32*STRH halfs
    float*  sbh  = (float*)(smraw + 2 * 32 * STRH * 2);          // 768 floats
    __half* sXI  = (__half*)(sbh + 768);                         // 16 warps x 16 x STRW halfs

    const int tid  = threadIdx.x;
    const int lane = tid & 31;
    const int w    = tid >> 5;
    const int w8   = w & 7;
    const int mh   = w >> 3;
    const int gr   = lane >> 2;
    const int tig  = lane & 3;

    const int c0 = blockIdx.x * 32;     // chain base (n)

    for (int i = tid; i < 768; i += 512) sbh[i] = cell_bh[i];
    for (int i = tid; i < 32 * STRH; i += 512) ((uint32_t*)h16)[i] = 0u;

    const uint32_t aoff = (uint32_t)((mh * 16 + (lane & 15)) * STRH * 2 + (lane >> 4) * 16);
    const uint32_t abase0 = smem_u32(h16) + aoff;
    const uint32_t abase1 = smem_u32(h16 + 32 * STRH) + aoff;

    __half* sxw = sXI + w * 16 * STRW;
    const uint32_t sxw_b = smem_u32(sxw);

    const uint4* bb = g_Bh4 + (size_t)4 * (96 * 8 * 32);   // cell_wh fragments

    float hold[2][4][2];
#pragma unroll
    for (int a = 0; a < 2; a++)
#pragma unroll
        for (int b = 0; b < 4; b++) { hold[a][b][0] = 0.f; hold[a][b][1] = 0.f; }

    __syncthreads();

    for (int j = 0; j < T_; j++) {
#pragma unroll
        for (int it = 0; it < 6; it++) {
            int id   = it * 32 + lane;
            int lrow = id & 15;
            int rem  = id >> 4;
            int gate = rem >> 2;
            int q    = rem & 3;
            int n    = c0 + mh * 16 + lrow;
            const __half* src = g_GI16 + ((size_t)(j * 64 + n)) * 768
                                + gate * 256 + w8 * 32 + q * 8;
            uint32_t dst = sxw_b + (uint32_t)(lrow * (STRW * 2) + gate * 64 + q * 16);
            asm volatile("cp.async.cg.shared.global [%0], [%1], 16;"
                         :: "r"(dst), "l"(src));
        }
        asm volatile("cp.async.commit_group;");

        const uint32_t abase = (j & 1) ? abase1 : abase0;
        float acc[3][4][4];
#pragma unroll
        for (int g = 0; g < 3; g++)
#pragma unroll
            for (int nt = 0; nt < 4; nt++)
#pragma unroll
                for (int i = 0; i < 4; i++) acc[g][nt][i] = 0.f;

#pragma unroll
        for (int kc2 = 0; kc2 < 8; kc2++) {
            uint32_t a0[4], a1[4];
            {
                uint32_t addr = abase + (uint32_t)(kc2 * 64);
                asm volatile("ldmatrix.sync.aligned.m8n8.x4.shared.b16 {%0,%1,%2,%3}, [%4];"
                             : "=r"(a0[0]), "=r"(a0[1]), "=r"(a0[2]), "=r"(a0[3]) : "r"(addr));
                asm volatile("ldmatrix.sync.aligned.m8n8.x4.shared.b16 {%0,%1,%2,%3}, [%4];"
                             : "=r"(a1[0]), "=r"(a1[1]), "=r"(a1[2]), "=r"(a1[3]) : "r"(addr + 32));
            }
#pragma unroll
            for (int g = 0; g < 3; g++) {
                uint4 bv[4];
#pragma unroll
                for (int nt = 0; nt < 4; nt++)
                    bv[nt] = __ldg(bb + ((size_t)((g * 32 + w8 * 4 + nt) * 8 + kc2)) * 32 + lane);
#pragma unroll
                for (int nt = 0; nt < 4; nt++) {
                    mma_f16(acc[g][nt], a0[0], a0[1], a0[2], a0[3], bv[nt].x, bv[nt].y);
                    mma_f16(acc[g][nt], a1[0], a1[1], a1[2], a1[3], bv[nt].z, bv[nt].w);
                }
            }
        }

        asm volatile("cp.async.wait_group 0;" ::: "memory");
        __syncwarp();

        __half* hnext = h16 + ((j & 1) ^ 1) * (32 * STRH);
#pragma unroll
        for (int nt = 0; nt < 4; nt++) {
            const int lcol = nt * 8 + 2 * tig;
            const int colb = w8 * 32 + lcol;
#pragma unroll
            for (int rw = 0; rw < 2; rw++) {
                const int lrow = rw * 8 + gr;
                const int row  = mh * 16 + lrow;
                const __half* xr = sxw + lrow * STRW + lcol;
                float2 xir = __half22float2(*(const __half2*)(xr));
                float2 xiz = __half22float2(*(const __half2*)(xr + 32));
                float2 xin = __half22float2(*(const __half2*)(xr + 64));

                float ghr0 = acc[0][nt][rw * 2 + 0] + sbh[colb];
                float ghr1 = acc[0][nt][rw * 2 + 1] + sbh[colb + 1];
                float ghz0 = acc[1][nt][rw * 2 + 0] + sbh[256 + colb];
                float ghz1 = acc[1][nt][rw * 2 + 1] + sbh[256 + colb + 1];
                float ghn0 = acc[2][nt][rw * 2 + 0] + sbh[512 + colb];
                float ghn1 = acc[2][nt][rw * 2 + 1] + sbh[512 + colb + 1];

                float r0 = __fdividef(1.f, 1.f + __expf(-(xir.x + ghr0)));
                float r1 = __fdividef(1.f, 1.f + __expf(-(xir.y + ghr1)));
                float z0 = __fdividef(1.f, 1.f + __expf(-(xiz.x + ghz0)));
                float z1 = __fdividef(1.f, 1.f + __expf(-(xiz.y + ghz1)));
                float n0, n1;
                asm("tanh.approx.f32 %0, %1;" : "=f"(n0) : "f"(xin.x + r0 * ghn0));
                asm("tanh.approx.f32 %0, %1;" : "=f"(n1) : "f"(xin.y + r1 * ghn1));

                float h0 = (1.f - z0) * n0 + z0 * hold[rw][nt][0];
                float h1 = (1.f - z1) * n1 + z1 * hold[rw][nt][1];
                hold[rw][nt][0] = h0;
                hold[rw][nt][1] = h1;

                *(__half2*)&hnext[row * STRH + colb] = __floats2half2_rn(h0, h1);
                *(float2*)(g_H2 + ((size_t)(j * 64 + c0 + row)) * 256 + colb)
                    = make_float2(h0, h1);
            }
        }
        __syncthreads();
    }
}

// ---------------------------------------------------------------------------
// matvec: fp32 weights, float4 loads (8 warps)
// ---------------------------------------------------------------------------
__device__ __forceinline__ void matvec8(float* __restrict__ y,
                                        const float* __restrict__ W,
                                        const float* __restrict__ b,
                                        const float* __restrict__ x,
                                        int Nout, int K)
{
    int tid  = threadIdx.x;
    int lane = tid & 31, warp = tid >> 5;
    int s = lane & 7, og = lane >> 3;
    for (int ob = warp * 4; ob < Nout; ob += 32) {
        int o = ob + og;
        bool valid = (o < Nout);
        const float* w = W + (size_t)(valid ? o : ob) * K;
        float acc = 0.f;
        for (int k = s * 4; k < K; k += 32) {
            float4 wv = *(const float4*)(w + k);
            float4 xv = *(const float4*)(x + k);
            acc += wv.x * xv.x + wv.y * xv.y + wv.z * xv.z + wv.w * xv.w;
        }
        acc += __shfl_down_sync(0xffffffffu, acc, 4);
        acc += __shfl_down_sync(0xffffffffu, acc, 2);
        acc += __shfl_down_sync(0xffffffffu, acc, 1);
        if (s == 0 && valid) y[o] = b ? (acc + b[o]) : acc;
    }
}

// ---------------------------------------------------------------------------
// D2: heads + SINGLE-PASS attention (R16 proven). One block per (t,n).
// ---------------------------------------------------------------------------
__global__ __launch_bounds__(256)
void decoder_heads(const float* __restrict__ pointer_w, const float* __restrict__ pointer_b,
                   const float* __restrict__ actor_w, const float* __restrict__ actor_b,
                   const float* __restrict__ critic_w, const float* __restrict__ critic_b,
                   const int* __restrict__ a_idx, const int* __restrict__ p_idx,
                   float* __restrict__ out)
{
    const int tn = blockIdx.x;            // t*64 + n
    const int tid = threadIdx.x;
    const int lane = tid & 31;
    const int w    = tid >> 5;

    __shared__ float sh_h[256];
    __shared__ float sh_q[256];
    __shared__ float szz[8 * 256];        // per-warp zz partials
    __shared__ float sh_zz[256];
    __shared__ float sh_pl[64];
    __shared__ float sh_al[16];
    __shared__ float sh_v[4];
    __shared__ float s_max, s_sum;

    sh_h[tid] = g_H2[(size_t)tn * 256 + tid];
    sh_q[tid] = g_Q [(size_t)tn * 256 + tid];
    __syncthreads();

    matvec8(sh_pl, pointer_w, pointer_b, sh_h, 64, 256);
    matvec8(sh_v,  critic_w,  critic_b,  sh_h, 1, 256);

    // ---- single-pass attention over this chain's 128 keys
    const __half* Kc = g_K16 + (size_t)tn * (2 * 64 * 256);   // [128][256] fp16
    {
        float qv[8];
        const float* qp = sh_q + lane * 8;
#pragma unroll
        for (int j2 = 0; j2 < 8; j2++) qv[j2] = qp[j2];

        float zzl[8];
#pragma unroll
        for (int j2 = 0; j2 < 8; j2++) zzl[j2] = 0.f;

#pragma unroll 4
        for (int r = 0; r < 16; r++) {
            int k = w * 16 + r;
            uint4 kv = __ldg((const uint4*)(Kc + (size_t)k * 256 + lane * 8));
            const __half2* hp = (const __half2*)&kv;
            float kf[8];
#pragma unroll
            for (int p = 0; p < 4; p++) {
                float2 f = __half22float2(hp[p]);
                kf[2 * p]     = f.x;
                kf[2 * p + 1] = f.y;
            }
            float part = 0.f;
#pragma unroll
            for (int j2 = 0; j2 < 8; j2++) part += kf[j2] * qv[j2];
#pragma unroll
            for (int o = 16; o > 0; o >>= 1)
                part += __shfl_xor_sync(0xffffffffu, part, o);
#pragma unroll
            for (int j2 = 0; j2 < 8; j2++) zzl[j2] += part * kf[j2];
        }
#pragma unroll
        for (int j2 = 0; j2 < 8; j2++) szz[w * 256 + lane * 8 + j2] = zzl[j2];
    }
    __syncthreads();

    if (tid < 32) {
        float m = fmaxf(sh_pl[tid], sh_pl[tid + 32]);
#pragma unroll
        for (int o = 16; o > 0; o >>= 1) m = fmaxf(m, __shfl_xor_sync(0xffffffffu, m, o));
        if (tid == 0) s_max = m;
    }
    __syncthreads();
    if (tid < 64) sh_pl[tid] = __expf(sh_pl[tid] - s_max);
    __syncthreads();
    if (tid < 32) {
        float s = sh_pl[tid] + sh_pl[tid + 32];
#pragma unroll
        for (int o = 16; o > 0; o >>= 1) s += __shfl_xor_sync(0xffffffffu, s, o);
        if (tid == 0) s_sum = s;
    }

    {
        float acc = 0.f;
#pragma unroll
        for (int w2 = 0; w2 < 8; w2++) acc += szz[w2 * 256 + tid];
        sh_zz[tid] = acc;
    }
    __syncthreads();

    matvec8(sh_al, actor_w, actor_b, sh_zz, 16, 256);
    __syncthreads();
    if (tid < 32) {
        float v = (tid < 16) ? sh_al[tid] : -1e30f;
        float m = v;
#pragma unroll
        for (int o = 16; o > 0; o >>= 1) m = fmaxf(m, __shfl_xor_sync(0xffffffffu, m, o));
        float e = (tid < 16) ? __expf(v - m) : 0.f;
        float s = e;
#pragma unroll
        for (int o = 16; o > 0; o >>= 1) s += __shfl_xor_sync(0xffffffffu, s, o);
        if (tid < 16) sh_al[tid] = e / s;
    }
    __syncthreads();

    float* orow = out + (size_t)tn * 339;
    if (tid == 0) {
        orow[0] = (float)a_idx[tn];
        orow[1] = (float)p_idx[tn];
        orow[2] = sh_v[0];
    }
    orow[3 + tid] = sh_h[tid];
    if (tid < 16) orow[259 + tid] = sh_al[tid];
    if (tid < 64) orow[275 + tid] = sh_pl[tid] / s_sum;
}

// ---------------------------------------------------------------------------
// Launch — single stream. ONE change vs R16: decoder_h -> decoder_h_mma
// (GI fp16, cell_wh fragments in permute slice 4; cvt_cellwh removed).
// ---------------------------------------------------------------------------
extern "C" void kernel_launch(void* const* d_in, const int* in_sizes, int n_in,
                              void* d_out, int out_size)
{
    const float* condition = (const float*)d_in[0];
    const int*   lines     = (const int*)  d_in[1];
    const int*   a_idx     = (const int*)  d_in[2];
    const int*   p_idx     = (const int*)  d_in[3];
    const float* embed     = (const float*)d_in[4];
    const float* aemb      = (const float*)d_in[5];
    const float* gru_wi_f  = (const float*)d_in[6];
    const float* gru_wh_f  = (const float*)d_in[7];
    const float* gru_bi_f  = (const float*)d_in[8];
    const float* gru_bh_f  = (const float*)d_in[9];
    const float* gru_wi_b  = (const float*)d_in[10];
    const float* gru_wh_b  = (const float*)d_in[11];
    const float* gru_bi_b  = (const float*)d_in[12];
    const float* gru_bh_b  = (const float*)d_in[13];
    const float* f_w1      = (const float*)d_in[14];
    const float* f_b1      = (const float*)d_in[15];
    const float* f_w2      = (const float*)d_in[16];
    const float* f_b2      = (const float*)d_in[17];
    const float* cell_wi   = (const float*)d_in[18];
    const float* cell_wh   = (const float*)d_in[19];
    const float* cell_bi   = (const float*)d_in[20];
    const float* cell_bh   = (const float*)d_in[21];
    const float* critic_w  = (const float*)d_in[22];
    const float* critic_b  = (const float*)d_in[23];
    const float* pointer_w = (const float*)d_in[24];
    const float* pointer_b = (const float*)d_in[25];
    const float* actor_w   = (const float*)d_in[26];
    const float* actor_b   = (const float*)d_in[27];
    const float* query_w   = (const float*)d_in[28];
    const float* query_b   = (const float*)d_in[29];
    float* out = (float*)d_out;

    void *pXF1_, *pXF2_, *pGI_, *pH2_, *pQ_;
    cudaGetSymbolAddress(&pXF1_, g_XF1);
    cudaGetSymbolAddress(&pXF2_, g_XF2);
    cudaGetSymbolAddress(&pGI_,  g_GI16);
    cudaGetSymbolAddress(&pH2_,  g_H2);
    cudaGetSymbolAddress(&pQ_,   g_Q);
    float* pXF1 = (float*)pXF1_;
    float* pXF2 = (float*)pXF2_;
    float* pGI  = (float*)pGI_;   // fp16 storage, written via outHalf=1
    float* pH2  = (float*)pH2_;
    float* pQ   = (float*)pQ_;

    const int SMEM_REC = 2 * 32 * STRH * 2 + 768 * 4 + 16 * 16 * STRW * 2 + 32 * 4;
    cudaFuncSetAttribute(recur_kernel, cudaFuncAttributeMaxDynamicSharedMemorySize, SMEM_REC);
    cudaFuncSetAttribute(decoder_h_mma, cudaFuncAttributeMaxDynamicSharedMemorySize, SMEM_REC);

    // 0) weight permutes (5 slices incl. cell_wh)
    permute_w16<<<480, 256>>>(gru_wh_f, gru_wh_b, gru_wi_f, gru_wi_b, cell_wh);

    // 1) XI projections via fp16 MMA
    xi_mma<<<256, 512>>>(lines, embed, gru_bi_f, gru_bi_b);

    // 2) decoder MLP + cell input gates (gi -> fp16)
    gemm_k<<<dim3(64, 2), 256>>>(1, nullptr, f_w1, f_b1, pXF1,
                                 256, 320, 1, 0, condition, aemb, a_idx);
    gemm_k<<<dim3(64, 2), 256>>>(2, pXF1, f_w2, f_b2, pXF2,
                                 256, 256, 1, 0, nullptr, nullptr, nullptr);
    gemm_k<<<dim3(64, 6), 256>>>(2, pXF2, cell_wi, cell_bi, pGI,
                                 768, 256, 0, 1, nullptr, nullptr, nullptr);

    // 3) persistent fp16-MMA recurrence (R11, untouched)
    recur_kernel<<<128, 512, SMEM_REC>>>(p_idx, gru_bh_f, gru_bh_b);

    // 4) decoder: h-chain via MMA, batched q GEMM, single-pass heads
    decoder_h_mma<<<2, 512, SMEM_REC>>>(cell_bh);
    gemm_k<<<dim3(64, 2), 256>>>(2, pH2, query_w, query_b, pQ,
                                 256, 256, 0, 0, nullptr, nullptr, nullptr);
    decoder_heads<<<2048, 256>>>(pointer_w, pointer_b, actor_w, actor_b,
                                 critic_w, critic_b, a_idx, p_idx, out);
}